// round 9
// baseline (speedup 1.0000x reference)
#include <cuda_runtime.h>
#include <math.h>

#define Bq   4
#define Cc   96
#define HWp  16384
#define NTOT (Bq*Cc*HWp)          // 6291456
#define CR3  36                    // new conv smem row stride (ull)
#define CTILE (66*CR3)             // 2376 ull per channel tile

typedef unsigned long long ull;

__device__ __forceinline__ ull pk2(float lo, float hi) {
    ull r; asm("mov.b64 %0,{%1,%2};" : "=l"(r) : "f"(lo), "f"(hi)); return r;
}
__device__ __forceinline__ void upk(ull v, float& lo, float& hi) {
    asm("mov.b64 {%0,%1},%2;" : "=f"(lo), "=f"(hi) : "l"(v));
}
__device__ __forceinline__ void ffma2(ull& d, ull a, ull b) {
    asm("fma.rn.f32x2 %0,%1,%2,%0;" : "+l"(d) : "l"(a), "l"(b));
}
__device__ __forceinline__ float gelu_ex(float x) {
    return 0.5f * x * (1.f + erff(x * 0.70710678118654752f));
}
__device__ __forceinline__ unsigned smem_u32(const void* p) {
    return (unsigned)__cvta_generic_to_shared(p);
}
__device__ __forceinline__ void cp16(unsigned dst, const void* src, int n) {
    asm volatile("cp.async.cg.shared.global [%0],[%1],16,%2;" :: "r"(dst), "l"(src), "r"(n));
}
#define CP_COMMIT() asm volatile("cp.async.commit_group;")
#define CP_WAIT0()  asm volatile("cp.async.wait_group 0;")

// ---------------- device scratch ----------------
__device__ ull   g_xi[NTOT];        // interleaved (x1,x2) pairs, CHW
__device__ ull   g_weffP[96*96*9];  // (w1eff,w2eff) pairs
__device__ float g_DT[128*128];
__device__ ull   g_DpD[128*128];    // dup pairs for DCT stage-1
__device__ ull   g_WcombP[96*96];   // dup
__device__ float g_bcomb[96];
__device__ ull   g_W1P[96*384];     // dup, [k*384+j]
__device__ ull   g_W2P[384*96];     // dup, [j*96+i]
__device__ float g_tokA[NTOT];
__device__ float g_tokB[NTOT];
__device__ float g_cross[NTOT];
__device__ float g_dct[NTOT];
__device__ float g_energy[Bq*HWp];
__device__ float g_scale[Bq];

// ---------------- interleave x1,x2 into pair array ----------------
__global__ void k_ilv(const float* __restrict__ x1, const float* __restrict__ x2) {
    int g = blockIdx.x * blockDim.x + threadIdx.x;   // NTOT/4
    float4 a = ((const float4*)x1)[g];
    float4 b = ((const float4*)x2)[g];
    ((float4*)g_xi)[2 * g]     = make_float4(a.x, b.x, a.y, b.y);
    ((float4*)g_xi)[2 * g + 1] = make_float4(a.z, b.z, a.w, b.w);
}

// ---------------- LDC effective weights, packed (w1,w2) ----------------
__global__ void k_weffP(const float* __restrict__ w1, const float* __restrict__ lm1,
                        const float* __restrict__ th1,
                        const float* __restrict__ w2, const float* __restrict__ lm2,
                        const float* __restrict__ th2) {
    int t = blockIdx.x * 256 + threadIdx.x;
    if (t >= 96 * 96) return;
    const float* ws1 = w1 + t * 9;
    const float* ws2 = w2 + t * 9;
    float s1 = 0.f, s2 = 0.f;
#pragma unroll
    for (int k = 0; k < 9; k++) { s1 += ws1[k]; s2 += ws2[k]; }
    float sc1 = 1.f - th1[0] * lm1[t] * s1;
    float sc2 = 1.f - th2[0] * lm2[t] * s2;
    ull* o = g_weffP + t * 9;
#pragma unroll
    for (int k = 0; k < 9; k++) o[k] = pk2(ws1[k], ws2[k]);
    o[4] = pk2(ws1[4] * sc1, ws2[4] * sc2);
}

// ---------------- init: DCT-II matrices ----------------
__global__ void k_init_dct() {
    int t = blockIdx.x * blockDim.x + threadIdx.x;   // 16384
    int k = t >> 7, i = t & 127;
    float arg = (float)((2 * i + 1) * k) * (1.0f / 256.0f);
    float v = cospif(arg) * 0.125f;
    if (k == 0) v *= 0.70710678118654752440f;
    g_DT[i * 128 + k] = v;
    g_DpD[((k >> 1) * 128 + i) * 2 + (k & 1)] = pk2(v, v);
}

// ---------------- prep: Wcomb dup, bcomb, MLP dup transposes ----------------
__global__ void k_prep2(const float* __restrict__ qkv_w, const float* __restrict__ qkv_b,
                        const float* __restrict__ proj_w, const float* __restrict__ proj_b,
                        const float* __restrict__ w1, const float* __restrict__ w2) {
    int blk = blockIdx.x, tid = threadIdx.x;
    if (blk < 96) {
        if (tid < 96) {
            float s = 0.f;
            for (int m = 0; m < 96; m++)
                s += proj_w[blk * 96 + m] * qkv_w[(192 + m) * 96 + tid];
            g_WcombP[tid * 96 + blk] = pk2(s, s);
        }
    } else if (blk == 96) {
        if (tid < 96) {
            float s = proj_b[tid];
            for (int m = 0; m < 96; m++)
                s += proj_w[tid * 96 + m] * qkv_b[192 + m];
            g_bcomb[tid] = s;
        }
    } else {
        int t = (blk - 97) * 256 + tid;
        if (t < 96 * 384) {
            { int k = t / 384, j = t % 384; float v = w1[j * 96 + k]; g_W1P[t] = pk2(v, v); }
            { int k = t / 96,  i = t % 96;  float v = w2[i * 384 + k]; g_W2P[t] = pk2(v, v); }
        }
    }
}

// ---------------- fused double conv + residual ----------------
// 8 pixels (4r x 2c) and 4 output channels per thread; tile 64x32 px.
// dynamic smem: sIn[2 buf][2 ch][66*36 ull] = 76032 B
__global__ void __launch_bounds__(256, 2)
k_conv() {
    extern __shared__ __align__(16) ull sIn[];
    __shared__ __align__(16) ull wS[2][2][4][10];     // [buf][ch][co][tap]
    __shared__ int2 slotS[5][256];                    // {goff or -1/-2, smem ull off}
    int tid = threadIdx.x;
    int b   = blockIdx.z;
    int cob = blockIdx.y * 4;                         // 24 co-blocks
    int bt  = blockIdx.x;                             // 8 tiles: 2 row x 4 col
    int y0  = (bt >> 2) * 64, x0 = (bt & 3) * 32;
    const ull* Xb = g_xi + (size_t)b * 96 * HWp;
    int ty = tid >> 4, tx = tid & 15;
    int rbase = ty * 4;
    int cbase = tx * 2 + 1;
    unsigned sbase = smem_u32(sIn);

    // channel-invariant load slots: 66 rows x 18 chunks (16B = 2 ull)
#pragma unroll
    for (int n = 0; n < 5; n++) {
        int s = tid + n * 256;
        if (s < 1188) {
            int r = s / 18, ch2 = s % 18;
            int gy = y0 - 1 + r;
            int gx = x0 - 2 + 2 * ch2;
            bool ok = (gy >= 0) && (gy < 128) && (gx >= 0) && (gx < 128);
            slotS[n][tid] = make_int2(ok ? (gy * 128 + gx) : -1, r * CR3 + 2 * ch2);
        } else {
            slotS[n][tid] = make_int2(-2, 0);
        }
    }
    __syncthreads();

    auto issue = [&](int st, int buf) {
#pragma unroll
        for (int c2 = 0; c2 < 2; c2++) {
            size_t gofs = (size_t)(2 * st + c2) * (HWp * 8);
            unsigned so = sbase + (unsigned)((buf * 2 + c2) * (CTILE * 8));
#pragma unroll
            for (int n = 0; n < 5; n++) {
                int2 sl = slotS[n][tid];
                if (sl.x != -2) {
                    int goff = sl.x < 0 ? 0 : sl.x;
                    cp16(so + (unsigned)sl.y * 8, (const char*)(Xb + goff) + gofs,
                         sl.x < 0 ? 0 : 16);
                }
            }
        }
        CP_COMMIT();
    };
    auto wload = [&](int st, int buf) {
        if (tid < 72) {
            int c2 = tid / 36, rr = tid % 36, co = rr / 9, k = rr % 9;
            wS[buf][c2][co][k] = g_weffP[((cob + co) * 96 + (2 * st + c2)) * 9 + k];
        }
    };

    issue(0, 0);
    wload(0, 0);

    ull acc[4][8];
#pragma unroll
    for (int i = 0; i < 4; i++)
#pragma unroll
        for (int j = 0; j < 8; j++) acc[i][j] = 0ULL;
    const ull TWO = pk2(2.f, 2.f);

    for (int st = 0; st < 48; st++) {
        int cur = st & 1;
        CP_WAIT0();
        __syncthreads();
        if (st < 47) { issue(st + 1, cur ^ 1); wload(st + 1, cur ^ 1); }

#pragma unroll
        for (int c2 = 0; c2 < 2; c2++) {
            const ull* tile = sIn + (cur * 2 + c2) * CTILE;
            ull rp[6][4];
#pragma unroll
            for (int i = 0; i < 6; i++)
#pragma unroll
                for (int j = 0; j < 4; j++)
                    rp[i][j] = tile[(rbase + i) * CR3 + cbase + j];

#pragma unroll
            for (int co = 0; co < 4; co++) {
#pragma unroll
                for (int ky = 0; ky < 3; ky++)
#pragma unroll
                    for (int kx = 0; kx < 3; kx++) {
                        ull w = wS[cur][c2][co][ky * 3 + kx];
#pragma unroll
                        for (int pr = 0; pr < 4; pr++) {
                            ffma2(acc[co][pr * 2 + 0], rp[pr + ky][kx],     w);
                            ffma2(acc[co][pr * 2 + 1], rp[pr + ky][kx + 1], w);
                        }
                    }
            }
            int cc = 2 * st + c2 - cob;
            if (cc >= 0 && cc < 4) {
#pragma unroll
                for (int pr = 0; pr < 4; pr++) {
                    ffma2(acc[cc][pr * 2 + 0], rp[pr + 1][1], TWO);
                    ffma2(acc[cc][pr * 2 + 1], rp[pr + 1][2], TWO);
                }
            }
        }
    }

    // store token-major: result = lo + hi (conv1(x1)+conv2(x2)+2(x1+x2))
#pragma unroll
    for (int pr = 0; pr < 4; pr++)
#pragma unroll
        for (int pc = 0; pc < 2; pc++) {
            float v[4];
#pragma unroll
            for (int co = 0; co < 4; co++) {
                float lo, hi; upk(acc[co][pr * 2 + pc], lo, hi);
                v[co] = lo + hi;
            }
            size_t tok = (size_t)b * HWp + (size_t)(y0 + ty * 4 + pr) * 128
                       + (x0 + tx * 2 + pc);
            *(float4*)(g_tokA + tok * 96 + cob) = make_float4(v[0], v[1], v[2], v[3]);
        }
}

// ---------------- swin attention (folded), smem-staged weights ----------------
__global__ void __launch_bounds__(256)
k_attn(const float* __restrict__ g1, const float* __restrict__ b1) {
    extern __shared__ __align__(16) ull dynsm[];
    ull*   wsm = dynsm;                       // 9216 ull
    float* tns = (float*)(dynsm + 9216);      // [8][960]
    int tid = threadIdx.x;
    int warp = tid >> 5, lane = tid & 31;
    int tokbase = blockIdx.x * 64 + warp * 8;
    float* tnw = tns + warp * 960;

#pragma unroll
    for (int i = 0; i < 18; i++) {
        int idx = tid + i * 256;
        cp16(smem_u32(wsm + 2 * idx), g_WcombP + 2 * idx, 16);
    }
    CP_COMMIT();

    float tv[8][3];
#pragma unroll
    for (int t = 0; t < 8; t++) {
        const float* tp = g_tokA + (size_t)(tokbase + t) * 96;
        float a = tp[lane], bb = tp[lane + 32], cc = tp[lane + 64];
        tv[t][0] = a; tv[t][1] = bb; tv[t][2] = cc;
        float s = a + bb + cc;
#pragma unroll
        for (int o = 16; o; o >>= 1) s += __shfl_xor_sync(0xffffffff, s, o);
        float m = s * (1.f / 96.f);
        float d0 = a - m, d1 = bb - m, d2 = cc - m;
        float q = d0 * d0 + d1 * d1 + d2 * d2;
#pragma unroll
        for (int o = 16; o; o >>= 1) q += __shfl_xor_sync(0xffffffff, q, o);
        float rstd = rsqrtf(q * (1.f / 96.f) + 1e-5f);
        tnw[lane * 10 + t]        = d0 * rstd * g1[lane]      + b1[lane];
        tnw[(lane + 32) * 10 + t] = d1 * rstd * g1[lane + 32] + b1[lane + 32];
        tnw[(lane + 64) * 10 + t] = d2 * rstd * g1[lane + 64] + b1[lane + 64];
    }
    CP_WAIT0();
    __syncthreads();

    ull acc[4][3];
#pragma unroll
    for (int p = 0; p < 4; p++) { acc[p][0] = 0; acc[p][1] = 0; acc[p][2] = 0; }
#pragma unroll 4
    for (int k = 0; k < 96; k++) {
        ull W0 = wsm[k * 96 + lane];
        ull W1 = wsm[k * 96 + lane + 32];
        ull W2 = wsm[k * 96 + lane + 64];
#pragma unroll
        for (int p = 0; p < 4; p++) {
            ull sp = *(const ull*)&tnw[k * 10 + 2 * p];
            ffma2(acc[p][0], sp, W0);
            ffma2(acc[p][1], sp, W1);
            ffma2(acc[p][2], sp, W2);
        }
    }
#pragma unroll
    for (int p = 0; p < 4; p++) {
#pragma unroll
        for (int c = 0; c < 3; c++) {
            float o0, o1; upk(acc[p][c], o0, o1);
            int ch = lane + 32 * c;
            g_tokB[(size_t)(tokbase + 2 * p) * 96 + ch]     = tv[2 * p][c]     + o0 + g_bcomb[ch];
            g_tokB[(size_t)(tokbase + 2 * p + 1) * 96 + ch] = tv[2 * p + 1][c] + o1 + g_bcomb[ch];
        }
    }
}

// ---------------- swin MLP, [ch][tok] smem, dup weights, j-halved ----------------
__global__ void __launch_bounds__(256)
k_mlp(const float* __restrict__ g2, const float* __restrict__ b2,
      const float* __restrict__ mb1, const float* __restrict__ mb2) {
    extern __shared__ float sm[];
    float* tnP = sm;            // [8][960]
    float* hsP = sm + 7680;     // [8][1920]
    int warp = threadIdx.x >> 5, lane = threadIdx.x & 31;
    int tokbase = blockIdx.x * 64 + warp * 8;
    float* tnw = tnP + warp * 960;
    float* hsw = hsP + warp * 1920;
    float tv[8][3];
#pragma unroll
    for (int t = 0; t < 8; t++) {
        const float* tp = g_tokB + (size_t)(tokbase + t) * 96;
        float a = tp[lane], bb = tp[lane + 32], cc = tp[lane + 64];
        tv[t][0] = a; tv[t][1] = bb; tv[t][2] = cc;
        float s = a + bb + cc;
#pragma unroll
        for (int o = 16; o; o >>= 1) s += __shfl_xor_sync(0xffffffff, s, o);
        float m = s * (1.f / 96.f);
        float d0 = a - m, d1 = bb - m, d2 = cc - m;
        float q = d0 * d0 + d1 * d1 + d2 * d2;
#pragma unroll
        for (int o = 16; o; o >>= 1) q += __shfl_xor_sync(0xffffffff, q, o);
        float rstd = rsqrtf(q * (1.f / 96.f) + 1e-5f);
        tnw[lane * 10 + t]        = d0 * rstd * g2[lane]      + b2[lane];
        tnw[(lane + 32) * 10 + t] = d1 * rstd * g2[lane + 32] + b2[lane + 32];
        tnw[(lane + 64) * 10 + t] = d2 * rstd * g2[lane + 64] + b2[lane + 64];
    }
    __syncwarp();
    ull oacc[4][3];
#pragma unroll
    for (int p = 0; p < 4; p++) { oacc[p][0] = 0; oacc[p][1] = 0; oacc[p][2] = 0; }

    for (int half = 0; half < 2; half++) {
        ull h[4][6];
#pragma unroll
        for (int p = 0; p < 4; p++)
#pragma unroll
            for (int r = 0; r < 6; r++) h[p][r] = 0;
        const ull* w1p = g_W1P + half * 192 + lane;
#pragma unroll 4
        for (int k = 0; k < 96; k++) {
            ull W[6];
#pragma unroll
            for (int r = 0; r < 6; r++) W[r] = w1p[k * 384 + 32 * r];
#pragma unroll
            for (int p = 0; p < 4; p++) {
                ull sp = *(const ull*)&tnw[k * 10 + 2 * p];
#pragma unroll
                for (int r = 0; r < 6; r++) ffma2(h[p][r], sp, W[r]);
            }
        }
#pragma unroll
        for (int p = 0; p < 4; p++)
#pragma unroll
            for (int r = 0; r < 6; r++) {
                int j = lane + 32 * r;
                float bias = mb1[half * 192 + j];
                float x0, x1; upk(h[p][r], x0, x1);
                hsw[j * 10 + 2 * p]     = gelu_ex(x0 + bias);
                hsw[j * 10 + 2 * p + 1] = gelu_ex(x1 + bias);
            }
        __syncwarp();
        const ull* w2p = g_W2P + (size_t)(half * 192) * 96;
#pragma unroll 4
        for (int j = 0; j < 192; j++) {
            ull U0 = w2p[j * 96 + lane];
            ull U1 = w2p[j * 96 + lane + 32];
            ull U2 = w2p[j * 96 + lane + 64];
#pragma unroll
            for (int p = 0; p < 4; p++) {
                ull hp = *(const ull*)&hsw[j * 10 + 2 * p];
                ffma2(oacc[p][0], hp, U0);
                ffma2(oacc[p][1], hp, U1);
                ffma2(oacc[p][2], hp, U2);
            }
        }
        __syncwarp();
    }
#pragma unroll
    for (int p = 0; p < 4; p++) {
#pragma unroll
        for (int c = 0; c < 3; c++) {
            float o0, o1; upk(oacc[p][c], o0, o1);
            int ch = lane + 32 * c;
            g_tokA[(size_t)(tokbase + 2 * p) * 96 + ch]     = tv[2 * p][c]     + o0 + mb2[ch];
            g_tokA[(size_t)(tokbase + 2 * p + 1) * 96 + ch] = tv[2 * p + 1][c] + o1 + mb2[ch];
        }
    }
}

// ---------------- transpose token-major -> CHW ----------------
__global__ void k_t2() {
    __shared__ float tile[32][33];
    int b = blockIdx.z, c0 = blockIdx.y * 32, p0 = blockIdx.x * 32;
    int tx = threadIdx.x, ty0 = threadIdx.y;
    for (int yy = ty0; yy < 32; yy += 8)
        tile[yy][tx] = g_tokA[(size_t)(b * HWp + p0 + yy) * 96 + c0 + tx];
    __syncthreads();
    for (int yy = ty0; yy < 32; yy += 8)
        g_cross[(size_t)(b * 96 + c0 + yy) * HWp + p0 + tx] = tile[tx][yy];
}

// ---------------- 2D DCT per (b,c) ----------------
__global__ void __launch_bounds__(256) k_dct() {
    extern __shared__ float sm[];
    float* Xs = sm;             // 16384
    float* Ys = sm + 16384;     // 16384
    int bc = blockIdx.x;
    int tid = threadIdx.x;
    const float4* src = (const float4*)(g_cross + (size_t)bc * HWp);
    float4* Xs4 = (float4*)Xs;
    for (int l = tid; l < 4096; l += 256) Xs4[l] = src[l];
    __syncthreads();

    int jq = tid & 31;
    int ig = tid >> 5;
    int j0 = 2 * jq, j2 = 64 + 2 * jq;

    for (int ii = 0; ii < 8; ii++) {
        int ip = ig + ii * 8;
        ull a00 = 0, a01 = 0, a10 = 0, a11 = 0;
        const ull* dp = g_DpD + ip * 256;
#pragma unroll 4
        for (int k = 0; k < 128; k++) {
            ull D0 = dp[2 * k], D1 = dp[2 * k + 1];
            ull xA = *(const ull*)&Xs[k * 128 + j0];
            ull xB = *(const ull*)&Xs[k * 128 + j2];
            ffma2(a00, xA, D0); ffma2(a01, xB, D0);
            ffma2(a10, xA, D1); ffma2(a11, xB, D1);
        }
        *(ull*)&Ys[(2 * ip) * 128 + j0]     = a00;
        *(ull*)&Ys[(2 * ip) * 128 + j2]     = a01;
        *(ull*)&Ys[(2 * ip + 1) * 128 + j0] = a10;
        *(ull*)&Ys[(2 * ip + 1) * 128 + j2] = a11;
    }
    __syncthreads();

    ull acc[8][4];
#pragma unroll
    for (int ii = 0; ii < 8; ii++)
#pragma unroll
        for (int q = 0; q < 4; q++) acc[ii][q] = 0;
#pragma unroll 2
    for (int k = 0; k < 128; k++) {
        ull dtA = *(const ull*)&g_DT[k * 128 + j0];
        ull dtB = *(const ull*)&g_DT[k * 128 + j2];
#pragma unroll
        for (int ii = 0; ii < 8; ii++) {
            int ip = ig + ii * 8;
            float y0 = Ys[(2 * ip) * 128 + k];
            float y1 = Ys[(2 * ip + 1) * 128 + k];
            ull Y0 = pk2(y0, y0), Y1 = pk2(y1, y1);
            ffma2(acc[ii][0], dtA, Y0); ffma2(acc[ii][1], dtB, Y0);
            ffma2(acc[ii][2], dtA, Y1); ffma2(acc[ii][3], dtB, Y1);
        }
    }
    float* dst = g_dct + (size_t)bc * HWp;
#pragma unroll
    for (int ii = 0; ii < 8; ii++) {
        int ip = ig + ii * 8;
        *(ull*)&dst[(2 * ip) * 128 + j0]     = acc[ii][0];
        *(ull*)&dst[(2 * ip) * 128 + j2]     = acc[ii][1];
        *(ull*)&dst[(2 * ip + 1) * 128 + j0] = acc[ii][2];
        *(ull*)&dst[(2 * ip + 1) * 128 + j2] = acc[ii][3];
    }
}

// ---------------- channel-mean |dct| (float4) ----------------
__global__ void k_energy() {
    int g = blockIdx.x * blockDim.x + threadIdx.x;   // 16384
    int b = g >> 12, p4 = g & 4095;
    const float4* base = (const float4*)(g_dct + (size_t)b * 96 * HWp) + p4;
    float4 s = make_float4(0.f, 0.f, 0.f, 0.f);
    for (int c = 0; c < 96; c++) {
        float4 v = base[(size_t)c * 4096];
        s.x += fabsf(v.x); s.y += fabsf(v.y); s.z += fabsf(v.z); s.w += fabsf(v.w);
    }
    float inv = 1.f / 96.f;
    s.x *= inv; s.y *= inv; s.z *= inv; s.w *= inv;
    ((float4*)(g_energy + b * HWp))[p4] = s;
}

// ---------------- top-96 via histogram threshold + rank sort ----------------
__global__ void __launch_bounds__(256)
k_topk(const float* __restrict__ fw1, const float* __restrict__ fb1,
       const float* __restrict__ fw2, const float* __restrict__ fb2) {
    extern __shared__ float e[];                 // 16384 floats
    int* hist = (int*)(e + 16384);               // 4096 ints (reused as cand)
    __shared__ int csum[256];
    __shared__ int s_T, s_cnt;
    __shared__ float tk[96];
    __shared__ float hh[24];
    int b = blockIdx.x, tid = threadIdx.x;

    const float4* src = (const float4*)(g_energy + b * HWp);
    float4* e4 = (float4*)e;
    for (int l = tid; l < 4096; l += 256) e4[l] = src[l];
    for (int l = tid; l < 4096; l += 256) hist[l] = 0;
    __syncthreads();
    for (int l = tid; l < 16384; l += 256) {
        int key = (int)(__float_as_uint(e[l]) >> 19);
        atomicAdd(&hist[key], 1);
    }
    __syncthreads();
    {
        int s = 0;
#pragma unroll
        for (int k = 0; k < 16; k++) s += hist[tid * 16 + k];
        csum[tid] = s;
    }
    __syncthreads();
    if (tid == 0) {
        int run = 0, cstar = 0;
        for (int c = 255; c >= 0; c--) {
            if (run + csum[c] >= 96) { cstar = c; break; }
            run += csum[c];
        }
        int T = cstar * 16;
        for (int k = 15; k >= 0; k--) {
            int bin = cstar * 16 + k;
            if (run + hist[bin] >= 96) { T = bin; break; }
            run += hist[bin];
        }
        s_T = T; s_cnt = 0;
    }
    __syncthreads();
    int T = s_T;
    float* cand = (float*)hist;
    __syncthreads();
    for (int l = tid; l < 16384; l += 256) {
        float v = e[l];
        if ((int)(__float_as_uint(v) >> 19) >= T) {
            int pos = atomicAdd(&s_cnt, 1);
            if (pos < 4096) cand[pos] = v;
        }
    }
    __syncthreads();
    int M = s_cnt; if (M > 4096) M = 4096;
    for (int i = tid; i < M; i += 256) {
        float v = cand[i];
        int r = 0;
        for (int j = 0; j < M; j++) {
            float u = cand[j];
            r += (u > v) || (u == v && j < i);
        }
        if (r < 96) tk[r] = v;
    }
    __syncthreads();
    if (tid < 24) {
        float s = fb1[tid];
        for (int k = 0; k < 96; k++) s += tk[k] * fw1[tid * 96 + k];
        hh[tid] = fmaxf(s, 0.f);
    }
    __syncthreads();
    if (tid == 0) {
        float a = fb2[0];
        for (int j = 0; j < 24; j++) a += hh[j] * fw2[j];
        g_scale[b] = 1.f + 1.f / (1.f + expf(-a));
    }
}

// ---------------- epilogue (float4) ----------------
__global__ void k_final(const float* __restrict__ x1, const float* __restrict__ x2,
                        float* __restrict__ out) {
    int i = blockIdx.x * blockDim.x + threadIdx.x;   // NTOT/4
    float s = g_scale[i / (96 * HWp / 4)];
    float4 c = ((const float4*)g_cross)[i];
    float4 a = ((const float4*)x1)[i];
    float4 b = ((const float4*)x2)[i];
    float4 o1, o2;
    o1.x = a.x + s * c.x; o1.y = a.y + s * c.y; o1.z = a.z + s * c.z; o1.w = a.w + s * c.w;
    o2.x = b.x + s * c.x; o2.y = b.y + s * c.y; o2.z = b.z + s * c.z; o2.w = b.w + s * c.w;
    ((float4*)out)[i]            = o1;
    ((float4*)out)[NTOT / 4 + i] = o2;
}

extern "C" void kernel_launch(void* const* d_in, const int* in_sizes, int n_in,
                              void* d_out, int out_size) {
    const float* x1     = (const float*)d_in[0];
    const float* x2     = (const float*)d_in[1];
    const float* w_tx1  = (const float*)d_in[2];
    const float* lm1    = (const float*)d_in[3];
    const float* theta1 = (const float*)d_in[4];
    const float* w_tx2  = (const float*)d_in[5];
    const float* lm2    = (const float*)d_in[6];
    const float* theta2 = (const float*)d_in[7];
    const float* ln1_g  = (const float*)d_in[8];
    const float* ln1_b  = (const float*)d_in[9];
    const float* qkv_w  = (const float*)d_in[10];
    const float* qkv_b  = (const float*)d_in[11];
    const float* proj_w = (const float*)d_in[12];
    const float* proj_b = (const float*)d_in[13];
    const float* ln2_g  = (const float*)d_in[14];
    const float* ln2_b  = (const float*)d_in[15];
    const float* mlp_w1 = (const float*)d_in[16];
    const float* mlp_b1 = (const float*)d_in[17];
    const float* mlp_w2 = (const float*)d_in[18];
    const float* mlp_b2 = (const float*)d_in[19];
    const float* fc_w1  = (const float*)d_in[20];
    const float* fc_b1  = (const float*)d_in[21];
    const float* fc_w2  = (const float*)d_in[22];
    const float* fc_b2  = (const float*)d_in[23];
    float* out = (float*)d_out;

    cudaFuncSetAttribute(k_conv, cudaFuncAttributeMaxDynamicSharedMemorySize, 76032);
    cudaFuncSetAttribute(k_attn, cudaFuncAttributeMaxDynamicSharedMemorySize, 104448);
    cudaFuncSetAttribute(k_mlp,  cudaFuncAttributeMaxDynamicSharedMemorySize, 92160);
    cudaFuncSetAttribute(k_dct,  cudaFuncAttributeMaxDynamicSharedMemorySize, 131072);
    cudaFuncSetAttribute(k_topk, cudaFuncAttributeMaxDynamicSharedMemorySize, 81920);

    // slot 4 (ncu capture) = k_conv
    k_ilv<<<NTOT / 4 / 256, 256>>>(x1, x2);
    k_weffP<<<36, 256>>>(w_tx1, lm1, theta1, w_tx2, lm2, theta2);
    k_prep2<<<241, 256>>>(qkv_w, qkv_b, proj_w, proj_b, mlp_w1, mlp_w2);
    k_conv<<<dim3(8, 24, 4), 256, 76032>>>();
    k_attn<<<1024, 256, 104448>>>(ln1_g, ln1_b);
    k_mlp<<<1024, 256, 92160>>>(ln2_g, ln2_b, mlp_b1, mlp_b2);
    k_init_dct<<<64, 256>>>();
    k_t2<<<dim3(512, 3, 4), dim3(32, 8)>>>();
    k_dct<<<384, 256, 131072>>>();
    k_energy<<<64, 256>>>();
    k_topk<<<4, 256, 81920>>>(fc_w1, fc_b1, fc_w2, fc_b2);
    k_final<<<NTOT / 4 / 256, 256>>>(x1, x2, out);
}

// round 14
// speedup vs baseline: 1.6576x; 1.6576x over previous
#include <cuda_runtime.h>
#include <math.h>
#include <stdint.h>

#define Bq   4
#define Cc   96
#define HWp  16384
#define NTOT (Bq*Cc*HWp)

typedef unsigned long long ull;

__device__ __forceinline__ ull pk2(float lo, float hi) {
    ull r; asm("mov.b64 %0,{%1,%2};" : "=l"(r) : "f"(lo), "f"(hi)); return r;
}
__device__ __forceinline__ void upk(ull v, float& lo, float& hi) {
    asm("mov.b64 {%0,%1},%2;" : "=f"(lo), "=f"(hi) : "l"(v));
}
__device__ __forceinline__ void ffma2(ull& d, ull a, ull b) {
    asm("fma.rn.f32x2 %0,%1,%2,%0;" : "+l"(d) : "l"(a), "l"(b));
}
__device__ __forceinline__ float gelu_ex(float x) {
    return 0.5f * x * (1.f + erff(x * 0.70710678118654752f));
}
__device__ __forceinline__ float tf32r(float x) {
    uint32_t r; asm("cvt.rna.tf32.f32 %0,%1;" : "=r"(r) : "f"(x));
    return __uint_as_float(r);
}
__device__ __forceinline__ unsigned smem_u32(const void* p) {
    return (unsigned)__cvta_generic_to_shared(p);
}
__device__ __forceinline__ void cp16(unsigned dst, const void* src, int n) {
    asm volatile("cp.async.cg.shared.global [%0],[%1],16,%2;" :: "r"(dst), "l"(src), "r"(n));
}
#define CP_COMMIT() asm volatile("cp.async.commit_group;")
#define CP_WAIT0()  asm volatile("cp.async.wait_group 0;")

// warp-level tf32 MMA, base-ISA
__device__ __forceinline__ void mma816(float* c, const float* a, float b0, float b1) {
    asm volatile("mma.sync.aligned.m16n8k8.row.col.f32.tf32.tf32.f32 "
        "{%0,%1,%2,%3},{%4,%5,%6,%7},{%8,%9},{%0,%1,%2,%3};"
        : "+f"(c[0]), "+f"(c[1]), "+f"(c[2]), "+f"(c[3])
        : "r"(__float_as_uint(a[0])), "r"(__float_as_uint(a[1])),
          "r"(__float_as_uint(a[2])), "r"(__float_as_uint(a[3])),
          "r"(__float_as_uint(b0)), "r"(__float_as_uint(b1)));
}

// ---------------- device scratch ----------------
__device__ float g_xT1[NTOT];       // token-major tf32(x1)
__device__ float g_xT2[NTOT];       // token-major tf32(x2)
__device__ float g_xsum[NTOT];      // token-major 2*(x1+x2), fp32 exact
__device__ float g_wT[2*3*9*3072];  // [img][kblk][tap][ci32][co96], tf32
__device__ float g_DT[128*128];
__device__ ull   g_DpD[128*128];
__device__ ull   g_WcombP[96*96];
__device__ float g_bcomb[96];
__device__ ull   g_W1P[96*384];
__device__ ull   g_W2P[384*96];
__device__ float g_tokA[NTOT];
__device__ float g_tokB[NTOT];
__device__ float g_cross[NTOT];
__device__ float g_dct[NTOT];
__device__ float g_energy[Bq*HWp];
__device__ float g_scale[Bq];

// ---------------- transpose CHW->token-major + tf32 + residual sum ----------------
__global__ void k_xT(const float* __restrict__ x1, const float* __restrict__ x2) {
    __shared__ float t1[32][33], t2[32][33];
    int b = blockIdx.z, c0 = blockIdx.y * 32, p0 = blockIdx.x * 32;
    int tx = threadIdx.x, ty = threadIdx.y;
    for (int yy = ty; yy < 32; yy += 8) {
        size_t idx = (size_t)(b * 96 + c0 + yy) * HWp + p0 + tx;
        t1[yy][tx] = x1[idx]; t2[yy][tx] = x2[idx];
    }
    __syncthreads();
    for (int yy = ty; yy < 32; yy += 8) {
        size_t o = (size_t)(b * HWp + p0 + yy) * 96 + c0 + tx;
        float a = t1[tx][yy], bb = t2[tx][yy];
        g_xT1[o] = tf32r(a);
        g_xT2[o] = tf32r(bb);
        g_xsum[o] = 2.f * (a + bb);
    }
}

// ---------------- LDC effective weights -> B tiles [ci32][co96], tf32 ----------------
__global__ void k_wprep(const float* __restrict__ w1, const float* __restrict__ lm1,
                        const float* __restrict__ th1,
                        const float* __restrict__ w2, const float* __restrict__ lm2,
                        const float* __restrict__ th2) {
    int t = blockIdx.x * 256 + threadIdx.x;
    if (t >= 96 * 96) return;
    int co = t / 96, ci = t % 96;
#pragma unroll
    for (int img = 0; img < 2; img++) {
        const float* ws = (img ? w2 : w1) + t * 9;
        const float* lm = img ? lm2 : lm1;
        float theta = img ? th2[0] : th1[0];
        float s = 0.f;
#pragma unroll
        for (int k = 0; k < 9; k++) s += ws[k];
        float sc = 1.f - theta * lm[t] * s;
#pragma unroll
        for (int tap = 0; tap < 9; tap++) {
            float v = ws[tap];
            if (tap == 4) v *= sc;
            g_wT[(size_t)((img * 3 + (ci >> 5)) * 9 + tap) * 3072 + (ci & 31) * 96 + co] = tf32r(v);
        }
    }
}

// ---------------- init: DCT-II matrices ----------------
__global__ void k_init_dct() {
    int t = blockIdx.x * blockDim.x + threadIdx.x;
    int k = t >> 7, i = t & 127;
    float arg = (float)((2 * i + 1) * k) * (1.0f / 256.0f);
    float v = cospif(arg) * 0.125f;
    if (k == 0) v *= 0.70710678118654752440f;
    g_DT[i * 128 + k] = v;
    g_DpD[((k >> 1) * 128 + i) * 2 + (k & 1)] = pk2(v, v);
}

// ---------------- prep: Wcomb dup, bcomb, MLP dup transposes ----------------
__global__ void k_prep2(const float* __restrict__ qkv_w, const float* __restrict__ qkv_b,
                        const float* __restrict__ proj_w, const float* __restrict__ proj_b,
                        const float* __restrict__ w1, const float* __restrict__ w2) {
    int blk = blockIdx.x, tid = threadIdx.x;
    if (blk < 96) {
        if (tid < 96) {
            float s = 0.f;
            for (int m = 0; m < 96; m++)
                s += proj_w[blk * 96 + m] * qkv_w[(192 + m) * 96 + tid];
            g_WcombP[tid * 96 + blk] = pk2(s, s);
        }
    } else if (blk == 96) {
        if (tid < 96) {
            float s = proj_b[tid];
            for (int m = 0; m < 96; m++)
                s += proj_w[tid * 96 + m] * qkv_b[192 + m];
            g_bcomb[tid] = s;
        }
    } else {
        int t = (blk - 97) * 256 + tid;
        if (t < 96 * 384) {
            { int k = t / 384, j = t % 384; float v = w1[j * 96 + k]; g_W1P[t] = pk2(v, v); }
            { int k = t / 96,  i = t % 96;  float v = w2[i * 384 + k]; g_W2P[t] = pk2(v, v); }
        }
    }
}

// ---------------- tensor-core conv via mma.sync tf32 (simple sync staging) ----------------
// CTA = (y row, batch). D[128px, 96co] in regs across 8 warps (32px x 48co each).
// A smem: [3 dy][130 px][36] floats. B smem: [32 k][100 co]. One cp.async group/tap.
#define A_PLANE (130*36)
#define SM_A_FLOATS (3*A_PLANE)                       // 14040
#define SMEM_CONV ((SM_A_FLOATS + 32*100) * 4)        // 68960
__global__ void __launch_bounds__(256, 2)
k_conv() {
    extern __shared__ float smf[];
    float* As = smf;
    float* Bs = smf + SM_A_FLOATS;
    int tid = threadIdx.x;
    int y = blockIdx.x, b = blockIdx.y;
    int lane = tid & 31, wid = tid >> 5;
    int grp = lane >> 2, qid = lane & 3;
    int m_base = (wid >> 1) * 32;
    int n_base = (wid & 1) * 48;

    float acc[2][6][4];
#pragma unroll
    for (int mt = 0; mt < 2; mt++)
#pragma unroll
        for (int nt = 0; nt < 6; nt++)
#pragma unroll
            for (int q = 0; q < 4; q++) acc[mt][nt][q] = 0.f;

    for (int s = 0; s < 6; s++) {
        int img = s / 3, kblk = s % 3;
        // stage A plane: 3 dy rows x 130 px x 32 ch (zero halo via src-size 0)
        {
            const float* base = (img ? g_xT2 : g_xT1) + (size_t)b * HWp * 96 + kblk * 32;
            for (int idx = tid; idx < 3120; idx += 256) {
                int r = idx >> 3, c4 = idx & 7;      // r = dy*130 + pxi
                int dy = r / 130, pxi = r % 130;
                int x = pxi - 1;
                int yy = y + dy - 1;
                bool ok = (x >= 0) && (x < 128) && (yy >= 0) && (yy < 128);
                const float* src = base + (size_t)((ok ? yy : 0) * 128 + (ok ? x : 0)) * 96 + c4 * 4;
                cp16(smem_u32(As + dy * A_PLANE + pxi * 36 + c4 * 4), src, ok ? 16 : 0);
            }
        }
        for (int tap = 0; tap < 9; tap++) {
            // stage B tile for this tap
            {
                const float* wsrc = g_wT + (size_t)((img * 3 + kblk) * 9 + tap) * 3072;
                for (int idx = tid; idx < 768; idx += 256) {
                    int k = idx / 24, ch = idx % 24;
                    cp16(smem_u32(Bs + k * 100 + ch * 4), wsrc + k * 96 + ch * 4, 16);
                }
            }
            CP_COMMIT();
            CP_WAIT0();
            __syncthreads();
            int dy = tap / 3, dx = tap % 3 - 1;
            const float* Ap = As + dy * A_PLANE;
#pragma unroll
            for (int kk = 0; kk < 4; kk++) {
                int k0 = kk * 8;
                float a[2][4];
#pragma unroll
                for (int mt = 0; mt < 2; mt++) {
                    int m0 = m_base + mt * 16 + grp + dx + 1;
                    a[mt][0] = Ap[m0 * 36 + k0 + qid];
                    a[mt][1] = Ap[(m0 + 8) * 36 + k0 + qid];
                    a[mt][2] = Ap[m0 * 36 + k0 + qid + 4];
                    a[mt][3] = Ap[(m0 + 8) * 36 + k0 + qid + 4];
                }
#pragma unroll
                for (int nt = 0; nt < 6; nt++) {
                    int nc = n_base + nt * 8 + grp;
                    float b0 = Bs[(k0 + qid) * 100 + nc];
                    float b1 = Bs[(k0 + qid + 4) * 100 + nc];
                    mma816(acc[0][nt], a[0], b0, b1);
                    mma816(acc[1][nt], a[1], b0, b1);
                }
            }
            __syncthreads();
        }
    }

    // epilogue: add exact residual, write token-major
    size_t tokbase = (size_t)b * HWp + (size_t)y * 128;
#pragma unroll
    for (int mt = 0; mt < 2; mt++) {
#pragma unroll
        for (int half = 0; half < 2; half++) {
            int m = m_base + mt * 16 + grp + half * 8;
            float* dst = g_tokA + (tokbase + m) * 96;
            const float* xs = g_xsum + (tokbase + m) * 96;
#pragma unroll
            for (int nt = 0; nt < 6; nt++) {
                int co = n_base + nt * 8 + 2 * qid;
                float2 sv = *(const float2*)(xs + co);
                float2 o;
                o.x = acc[mt][nt][half * 2 + 0] + sv.x;
                o.y = acc[mt][nt][half * 2 + 1] + sv.y;
                *(float2*)(dst + co) = o;
            }
        }
    }
}

// ---------------- swin attention (folded), smem-staged weights ----------------
__global__ void __launch_bounds__(256)
k_attn(const float* __restrict__ g1, const float* __restrict__ b1) {
    extern __shared__ __align__(16) ull dynsm[];
    ull*   wsm = dynsm;
    float* tns = (float*)(dynsm + 9216);
    int tid = threadIdx.x;
    int warp = tid >> 5, lane = tid & 31;
    int tokbase = blockIdx.x * 64 + warp * 8;
    float* tnw = tns + warp * 960;

#pragma unroll
    for (int i = 0; i < 18; i++) {
        int idx = tid + i * 256;
        cp16(smem_u32(wsm + 2 * idx), g_WcombP + 2 * idx, 16);
    }
    CP_COMMIT();

    float tv[8][3];
#pragma unroll
    for (int t = 0; t < 8; t++) {
        const float* tp = g_tokA + (size_t)(tokbase + t) * 96;
        float a = tp[lane], bb = tp[lane + 32], cc = tp[lane + 64];
        tv[t][0] = a; tv[t][1] = bb; tv[t][2] = cc;
        float s = a + bb + cc;
#pragma unroll
        for (int o = 16; o; o >>= 1) s += __shfl_xor_sync(0xffffffff, s, o);
        float m = s * (1.f / 96.f);
        float d0 = a - m, d1 = bb - m, d2 = cc - m;
        float q = d0 * d0 + d1 * d1 + d2 * d2;
#pragma unroll
        for (int o = 16; o; o >>= 1) q += __shfl_xor_sync(0xffffffff, q, o);
        float rstd = rsqrtf(q * (1.f / 96.f) + 1e-5f);
        tnw[lane * 10 + t]        = d0 * rstd * g1[lane]      + b1[lane];
        tnw[(lane + 32) * 10 + t] = d1 * rstd * g1[lane + 32] + b1[lane + 32];
        tnw[(lane + 64) * 10 + t] = d2 * rstd * g1[lane + 64] + b1[lane + 64];
    }
    CP_WAIT0();
    __syncthreads();

    ull acc[4][3];
#pragma unroll
    for (int p = 0; p < 4; p++) { acc[p][0] = 0; acc[p][1] = 0; acc[p][2] = 0; }
#pragma unroll 4
    for (int k = 0; k < 96; k++) {
        ull W0 = wsm[k * 96 + lane];
        ull W1 = wsm[k * 96 + lane + 32];
        ull W2 = wsm[k * 96 + lane + 64];
#pragma unroll
        for (int p = 0; p < 4; p++) {
            ull sp = *(const ull*)&tnw[k * 10 + 2 * p];
            ffma2(acc[p][0], sp, W0);
            ffma2(acc[p][1], sp, W1);
            ffma2(acc[p][2], sp, W2);
        }
    }
#pragma unroll
    for (int p = 0; p < 4; p++) {
#pragma unroll
        for (int c = 0; c < 3; c++) {
            float o0, o1; upk(acc[p][c], o0, o1);
            int ch = lane + 32 * c;
            g_tokB[(size_t)(tokbase + 2 * p) * 96 + ch]     = tv[2 * p][c]     + o0 + g_bcomb[ch];
            g_tokB[(size_t)(tokbase + 2 * p + 1) * 96 + ch] = tv[2 * p + 1][c] + o1 + g_bcomb[ch];
        }
    }
}

// ---------------- swin MLP ----------------
__global__ void __launch_bounds__(256)
k_mlp(const float* __restrict__ g2, const float* __restrict__ b2,
      const float* __restrict__ mb1, const float* __restrict__ mb2) {
    extern __shared__ float sm[];
    float* tnP = sm;
    float* hsP = sm + 7680;
    int warp = threadIdx.x >> 5, lane = threadIdx.x & 31;
    int tokbase = blockIdx.x * 64 + warp * 8;
    float* tnw = tnP + warp * 960;
    float* hsw = hsP + warp * 1920;
    float tv[8][3];
#pragma unroll
    for (int t = 0; t < 8; t++) {
        const float* tp = g_tokB + (size_t)(tokbase + t) * 96;
        float a = tp[lane], bb = tp[lane + 32], cc = tp[lane + 64];
        tv[t][0] = a; tv[t][1] = bb; tv[t][2] = cc;
        float s = a + bb + cc;
#pragma unroll
        for (int o = 16; o; o >>= 1) s += __shfl_xor_sync(0xffffffff, s, o);
        float m = s * (1.f / 96.f);
        float d0 = a - m, d1 = bb - m, d2 = cc - m;
        float q = d0 * d0 + d1 * d1 + d2 * d2;
#pragma unroll
        for (int o = 16; o; o >>= 1) q += __shfl_xor_sync(0xffffffff, q, o);
        float rstd = rsqrtf(q * (1.f / 96.f) + 1e-5f);
        tnw[lane * 10 + t]        = d0 * rstd * g2[lane]      + b2[lane];
        tnw[(lane + 32) * 10 + t] = d1 * rstd * g2[lane + 32] + b2[lane + 32];
        tnw[(lane + 64) * 10 + t] = d2 * rstd * g2[lane + 64] + b2[lane + 64];
    }
    __syncwarp();
    ull oacc[4][3];
#pragma unroll
    for (int p = 0; p < 4; p++) { oacc[p][0] = 0; oacc[p][1] = 0; oacc[p][2] = 0; }

    for (int half = 0; half < 2; half++) {
        ull h[4][6];
#pragma unroll
        for (int p = 0; p < 4; p++)
#pragma unroll
            for (int r = 0; r < 6; r++) h[p][r] = 0;
        const ull* w1p = g_W1P + half * 192 + lane;
#pragma unroll 4
        for (int k = 0; k < 96; k++) {
            ull W[6];
#pragma unroll
            for (int r = 0; r < 6; r++) W[r] = w1p[k * 384 + 32 * r];
#pragma unroll
            for (int p = 0; p < 4; p++) {
                ull sp = *(const ull*)&tnw[k * 10 + 2 * p];
#pragma unroll
                for (int r = 0; r < 6; r++) ffma2(h[p][r], sp, W[r]);
            }
        }
#pragma unroll
        for (int p = 0; p < 4; p++)
#pragma unroll
            for (int r = 0; r < 6; r++) {
                int j = lane + 32 * r;
                float bias = mb1[half * 192 + j];
                float x0, x1; upk(h[p][r], x0, x1);
                hsw[j * 10 + 2 * p]     = gelu_ex(x0 + bias);
                hsw[j * 10 + 2 * p + 1] = gelu_ex(x1 + bias);
            }
        __syncwarp();
        const ull* w2p = g_W2P + (size_t)(half * 192) * 96;
#pragma unroll 4
        for (int j = 0; j < 192; j++) {
            ull U0 = w2p[j * 96 + lane];
            ull U1 = w2p[j * 96 + lane + 32];
            ull U2 = w2p[j * 96 + lane + 64];
#pragma unroll
            for (int p = 0; p < 4; p++) {
                ull hp = *(const ull*)&hsw[j * 10 + 2 * p];
                ffma2(oacc[p][0], hp, U0);
                ffma2(oacc[p][1], hp, U1);
                ffma2(oacc[p][2], hp, U2);
            }
        }
        __syncwarp();
    }
#pragma unroll
    for (int p = 0; p < 4; p++) {
#pragma unroll
        for (int c = 0; c < 3; c++) {
            float o0, o1; upk(oacc[p][c], o0, o1);
            int ch = lane + 32 * c;
            g_tokA[(size_t)(tokbase + 2 * p) * 96 + ch]     = tv[2 * p][c]     + o0 + mb2[ch];
            g_tokA[(size_t)(tokbase + 2 * p + 1) * 96 + ch] = tv[2 * p + 1][c] + o1 + mb2[ch];
        }
    }
}

// ---------------- transpose token-major -> CHW ----------------
__global__ void k_t2() {
    __shared__ float tile[32][33];
    int b = blockIdx.z, c0 = blockIdx.y * 32, p0 = blockIdx.x * 32;
    int tx = threadIdx.x, ty0 = threadIdx.y;
    for (int yy = ty0; yy < 32; yy += 8)
        tile[yy][tx] = g_tokA[(size_t)(b * HWp + p0 + yy) * 96 + c0 + tx];
    __syncthreads();
    for (int yy = ty0; yy < 32; yy += 8)
        g_cross[(size_t)(b * 96 + c0 + yy) * HWp + p0 + tx] = tile[tx][yy];
}

// ---------------- 2D DCT per (b,c) ----------------
__global__ void __launch_bounds__(256) k_dct() {
    extern __shared__ float sm[];
    float* Xs = sm;
    float* Ys = sm + 16384;
    int bc = blockIdx.x;
    int tid = threadIdx.x;
    const float4* src = (const float4*)(g_cross + (size_t)bc * HWp);
    float4* Xs4 = (float4*)Xs;
    for (int l = tid; l < 4096; l += 256) Xs4[l] = src[l];
    __syncthreads();

    int jq = tid & 31;
    int ig = tid >> 5;
    int j0 = 2 * jq, j2 = 64 + 2 * jq;

    for (int ii = 0; ii < 8; ii++) {
        int ip = ig + ii * 8;
        ull a00 = 0, a01 = 0, a10 = 0, a11 = 0;
        const ull* dp = g_DpD + ip * 256;
#pragma unroll 4
        for (int k = 0; k < 128; k++) {
            ull D0 = dp[2 * k], D1 = dp[2 * k + 1];
            ull xA = *(const ull*)&Xs[k * 128 + j0];
            ull xB = *(const ull*)&Xs[k * 128 + j2];
            ffma2(a00, xA, D0); ffma2(a01, xB, D0);
            ffma2(a10, xA, D1); ffma2(a11, xB, D1);
        }
        *(ull*)&Ys[(2 * ip) * 128 + j0]     = a00;
        *(ull*)&Ys[(2 * ip) * 128 + j2]     = a01;
        *(ull*)&Ys[(2 * ip + 1) * 128 + j0] = a10;
        *(ull*)&Ys[(2 * ip + 1) * 128 + j2] = a11;
    }
    __syncthreads();

    ull acc[8][4];
#pragma unroll
    for (int ii = 0; ii < 8; ii++)
#pragma unroll
        for (int q = 0; q < 4; q++) acc[ii][q] = 0;
#pragma unroll 2
    for (int k = 0; k < 128; k++) {
        ull dtA = *(const ull*)&g_DT[k * 128 + j0];
        ull dtB = *(const ull*)&g_DT[k * 128 + j2];
#pragma unroll
        for (int ii = 0; ii < 8; ii++) {
            int ip = ig + ii * 8;
            float y0 = Ys[(2 * ip) * 128 + k];
            float y1 = Ys[(2 * ip + 1) * 128 + k];
            ull Y0 = pk2(y0, y0), Y1 = pk2(y1, y1);
            ffma2(acc[ii][0], dtA, Y0); ffma2(acc[ii][1], dtB, Y0);
            ffma2(acc[ii][2], dtA, Y1); ffma2(acc[ii][3], dtB, Y1);
        }
    }
    float* dst = g_dct + (size_t)bc * HWp;
#pragma unroll
    for (int ii = 0; ii < 8; ii++) {
        int ip = ig + ii * 8;
        *(ull*)&dst[(2 * ip) * 128 + j0]     = acc[ii][0];
        *(ull*)&dst[(2 * ip) * 128 + j2]     = acc[ii][1];
        *(ull*)&dst[(2 * ip + 1) * 128 + j0] = acc[ii][2];
        *(ull*)&dst[(2 * ip + 1) * 128 + j2] = acc[ii][3];
    }
}

// ---------------- channel-mean |dct| ----------------
__global__ void k_energy() {
    int g = blockIdx.x * blockDim.x + threadIdx.x;
    int b = g >> 12, p4 = g & 4095;
    const float4* base = (const float4*)(g_dct + (size_t)b * 96 * HWp) + p4;
    float4 s = make_float4(0.f, 0.f, 0.f, 0.f);
    for (int c = 0; c < 96; c++) {
        float4 v = base[(size_t)c * 4096];
        s.x += fabsf(v.x); s.y += fabsf(v.y); s.z += fabsf(v.z); s.w += fabsf(v.w);
    }
    float inv = 1.f / 96.f;
    s.x *= inv; s.y *= inv; s.z *= inv; s.w *= inv;
    ((float4*)(g_energy + b * HWp))[p4] = s;
}

// ---------------- top-96 via histogram threshold + rank sort ----------------
__global__ void __launch_bounds__(256)
k_topk(const float* __restrict__ fw1, const float* __restrict__ fb1,
       const float* __restrict__ fw2, const float* __restrict__ fb2) {
    extern __shared__ float e[];
    int* hist = (int*)(e + 16384);
    __shared__ int csum[256];
    __shared__ int s_T, s_cnt;
    __shared__ float tk[96];
    __shared__ float hh[24];
    int b = blockIdx.x, tid = threadIdx.x;

    const float4* src = (const float4*)(g_energy + b * HWp);
    float4* e4 = (float4*)e;
    for (int l = tid; l < 4096; l += 256) e4[l] = src[l];
    for (int l = tid; l < 4096; l += 256) hist[l] = 0;
    __syncthreads();
    for (int l = tid; l < 16384; l += 256) {
        int key = (int)(__float_as_uint(e[l]) >> 19);
        atomicAdd(&hist[key], 1);
    }
    __syncthreads();
    {
        int s = 0;
#pragma unroll
        for (int k = 0; k < 16; k++) s += hist[tid * 16 + k];
        csum[tid] = s;
    }
    __syncthreads();
    if (tid == 0) {
        int run = 0, cstar = 0;
        for (int c = 255; c >= 0; c--) {
            if (run + csum[c] >= 96) { cstar = c; break; }
            run += csum[c];
        }
        int T = cstar * 16;
        for (int k = 15; k >= 0; k--) {
            int bin = cstar * 16 + k;
            if (run + hist[bin] >= 96) { T = bin; break; }
            run += hist[bin];
        }
        s_T = T; s_cnt = 0;
    }
    __syncthreads();
    int T = s_T;
    float* cand = (float*)hist;
    __syncthreads();
    for (int l = tid; l < 16384; l += 256) {
        float v = e[l];
        if ((int)(__float_as_uint(v) >> 19) >= T) {
            int pos = atomicAdd(&s_cnt, 1);
            if (pos < 4096) cand[pos] = v;
        }
    }
    __syncthreads();
    int M = s_cnt; if (M > 4096) M = 4096;
    for (int i = tid; i < M; i += 256) {
        float v = cand[i];
        int r = 0;
        for (int j = 0; j < M; j++) {
            float u = cand[j];
            r += (u > v) || (u == v && j < i);
        }
        if (r < 96) tk[r] = v;
    }
    __syncthreads();
    if (tid < 24) {
        float s = fb1[tid];
        for (int k = 0; k < 96; k++) s += tk[k] * fw1[tid * 96 + k];
        hh[tid] = fmaxf(s, 0.f);
    }
    __syncthreads();
    if (tid == 0) {
        float a = fb2[0];
        for (int j = 0; j < 24; j++) a += hh[j] * fw2[j];
        g_scale[b] = 1.f + 1.f / (1.f + expf(-a));
    }
}

// ---------------- epilogue ----------------
__global__ void k_final(const float* __restrict__ x1, const float* __restrict__ x2,
                        float* __restrict__ out) {
    int i = blockIdx.x * blockDim.x + threadIdx.x;
    float s = g_scale[i / (96 * HWp / 4)];
    float4 c = ((const float4*)g_cross)[i];
    float4 a = ((const float4*)x1)[i];
    float4 b = ((const float4*)x2)[i];
    float4 o1, o2;
    o1.x = a.x + s * c.x; o1.y = a.y + s * c.y; o1.z = a.z + s * c.z; o1.w = a.w + s * c.w;
    o2.x = b.x + s * c.x; o2.y = b.y + s * c.y; o2.z = b.z + s * c.z; o2.w = b.w + s * c.w;
    ((float4*)out)[i]            = o1;
    ((float4*)out)[NTOT / 4 + i] = o2;
}

extern "C" void kernel_launch(void* const* d_in, const int* in_sizes, int n_in,
                              void* d_out, int out_size) {
    const float* x1     = (const float*)d_in[0];
    const float* x2     = (const float*)d_in[1];
    const float* w_tx1  = (const float*)d_in[2];
    const float* lm1    = (const float*)d_in[3];
    const float* theta1 = (const float*)d_in[4];
    const float* w_tx2  = (const float*)d_in[5];
    const float* lm2    = (const float*)d_in[6];
    const float* theta2 = (const float*)d_in[7];
    const float* ln1_g  = (const float*)d_in[8];
    const float* ln1_b  = (const float*)d_in[9];
    const float* qkv_w  = (const float*)d_in[10];
    const float* qkv_b  = (const float*)d_in[11];
    const float* proj_w = (const float*)d_in[12];
    const float* proj_b = (const float*)d_in[13];
    const float* ln2_g  = (const float*)d_in[14];
    const float* ln2_b  = (const float*)d_in[15];
    const float* mlp_w1 = (const float*)d_in[16];
    const float* mlp_b1 = (const float*)d_in[17];
    const float* mlp_w2 = (const float*)d_in[18];
    const float* mlp_b2 = (const float*)d_in[19];
    const float* fc_w1  = (const float*)d_in[20];
    const float* fc_b1  = (const float*)d_in[21];
    const float* fc_w2  = (const float*)d_in[22];
    const float* fc_b2  = (const float*)d_in[23];
    float* out = (float*)d_out;

    cudaFuncSetAttribute(k_conv, cudaFuncAttributeMaxDynamicSharedMemorySize, SMEM_CONV);
    cudaFuncSetAttribute(k_attn, cudaFuncAttributeMaxDynamicSharedMemorySize, 104448);
    cudaFuncSetAttribute(k_mlp,  cudaFuncAttributeMaxDynamicSharedMemorySize, 92160);
    cudaFuncSetAttribute(k_dct,  cudaFuncAttributeMaxDynamicSharedMemorySize, 131072);
    cudaFuncSetAttribute(k_topk, cudaFuncAttributeMaxDynamicSharedMemorySize, 81920);

    // slot 4 (ncu capture) = k_conv
    k_xT<<<dim3(512, 3, 4), dim3(32, 8)>>>(x1, x2);
    k_wprep<<<36, 256>>>(w_tx1, lm1, theta1, w_tx2, lm2, theta2);
    k_prep2<<<241, 256>>>(qkv_w, qkv_b, proj_w, proj_b, mlp_w1, mlp_w2);
    k_conv<<<dim3(128, 4), 256, SMEM_CONV>>>();
    k_attn<<<1024, 256, 104448>>>(ln1_g, ln1_b);
    k_mlp<<<1024, 256, 92160>>>(ln2_g, ln2_b, mlp_b1, mlp_b2);
    k_init_dct<<<64, 256>>>();
    k_t2<<<dim3(512, 3, 4), dim3(32, 8)>>>();
    k_dct<<<384, 256, 131072>>>();
    k_energy<<<64, 256>>>();
    k_topk<<<4, 256, 81920>>>(fc_w1, fc_b1, fc_w2, fc_b2);
    k_final<<<NTOT / 4 / 256, 256>>>(x1, x2, out);
}

// round 15
// speedup vs baseline: 2.8951x; 1.7465x over previous
#include <cuda_runtime.h>
#include <math.h>
#include <stdint.h>

#define Bq   4
#define Cc   96
#define HWp  16384
#define NTOT (Bq*Cc*HWp)

typedef unsigned long long ull;

__device__ __forceinline__ ull pk2(float lo, float hi) {
    ull r; asm("mov.b64 %0,{%1,%2};" : "=l"(r) : "f"(lo), "f"(hi)); return r;
}
__device__ __forceinline__ void upk(ull v, float& lo, float& hi) {
    asm("mov.b64 {%0,%1},%2;" : "=f"(lo), "=f"(hi) : "l"(v));
}
__device__ __forceinline__ void ffma2(ull& d, ull a, ull b) {
    asm("fma.rn.f32x2 %0,%1,%2,%0;" : "+l"(d) : "l"(a), "l"(b));
}
__device__ __forceinline__ float gelu_ex(float x) {
    return 0.5f * x * (1.f + erff(x * 0.70710678118654752f));
}
__device__ __forceinline__ float tf32r(float x) {
    uint32_t r; asm("cvt.rna.tf32.f32 %0,%1;" : "=r"(r) : "f"(x));
    return __uint_as_float(r);
}
__device__ __forceinline__ unsigned smem_u32(const void* p) {
    return (unsigned)__cvta_generic_to_shared(p);
}
__device__ __forceinline__ void cp16(unsigned dst, const void* src, int n) {
    asm volatile("cp.async.cg.shared.global [%0],[%1],16,%2;" :: "r"(dst), "l"(src), "r"(n));
}
#define CP_COMMIT() asm volatile("cp.async.commit_group;")
#define CP_WAIT0()  asm volatile("cp.async.wait_group 0;")

// warp-level tf32 MMA, base-ISA
__device__ __forceinline__ void mma816(float* c, const float* a, float b0, float b1) {
    asm volatile("mma.sync.aligned.m16n8k8.row.col.f32.tf32.tf32.f32 "
        "{%0,%1,%2,%3},{%4,%5,%6,%7},{%8,%9},{%0,%1,%2,%3};"
        : "+f"(c[0]), "+f"(c[1]), "+f"(c[2]), "+f"(c[3])
        : "r"(__float_as_uint(a[0])), "r"(__float_as_uint(a[1])),
          "r"(__float_as_uint(a[2])), "r"(__float_as_uint(a[3])),
          "r"(__float_as_uint(b0)), "r"(__float_as_uint(b1)));
}

// ---------------- device scratch ----------------
__device__ float g_xT1[NTOT];       // token-major tf32(x1)
__device__ float g_xT2[NTOT];       // token-major tf32(x2)
__device__ float g_xsum[NTOT];      // token-major 2*(x1+x2), fp32 exact
__device__ float g_wT[2*3*9*3072];  // conv B tiles [img][kblk][tap][ci32][co96], tf32
__device__ float g_Dt[128*128];     // D row-major [freq][pos]
__device__ float g_DT[128*128];     // D^T row-major [pos][freq]
__device__ ull   g_WcombP[96*96];
__device__ float g_bcomb[96];
__device__ float g_W1t[96*384];     // [k][j] tf32
__device__ float g_W2t[384*96];     // [k][co] tf32
__device__ float g_tokA[NTOT];
__device__ float g_tokB[NTOT];
__device__ float g_cross[NTOT];
__device__ float g_dct[NTOT];
__device__ float g_energy[Bq*HWp];
__device__ float g_scale[Bq];

// ---------------- transpose CHW->token-major + tf32 + residual sum ----------------
__global__ void k_xT(const float* __restrict__ x1, const float* __restrict__ x2) {
    __shared__ float t1[32][33], t2[32][33];
    int b = blockIdx.z, c0 = blockIdx.y * 32, p0 = blockIdx.x * 32;
    int tx = threadIdx.x, ty = threadIdx.y;
    for (int yy = ty; yy < 32; yy += 8) {
        size_t idx = (size_t)(b * 96 + c0 + yy) * HWp + p0 + tx;
        t1[yy][tx] = x1[idx]; t2[yy][tx] = x2[idx];
    }
    __syncthreads();
    for (int yy = ty; yy < 32; yy += 8) {
        size_t o = (size_t)(b * HWp + p0 + yy) * 96 + c0 + tx;
        float a = t1[tx][yy], bb = t2[tx][yy];
        g_xT1[o] = tf32r(a);
        g_xT2[o] = tf32r(bb);
        g_xsum[o] = 2.f * (a + bb);
    }
}

// ---------------- LDC effective weights -> conv B tiles, tf32 ----------------
__global__ void k_wprep(const float* __restrict__ w1, const float* __restrict__ lm1,
                        const float* __restrict__ th1,
                        const float* __restrict__ w2, const float* __restrict__ lm2,
                        const float* __restrict__ th2) {
    int t = blockIdx.x * 256 + threadIdx.x;
    if (t >= 96 * 96) return;
    int co = t / 96, ci = t % 96;
#pragma unroll
    for (int img = 0; img < 2; img++) {
        const float* ws = (img ? w2 : w1) + t * 9;
        const float* lm = img ? lm2 : lm1;
        float theta = img ? th2[0] : th1[0];
        float s = 0.f;
#pragma unroll
        for (int k = 0; k < 9; k++) s += ws[k];
        float sc = 1.f - theta * lm[t] * s;
#pragma unroll
        for (int tap = 0; tap < 9; tap++) {
            float v = ws[tap];
            if (tap == 4) v *= sc;
            g_wT[(size_t)((img * 3 + (ci >> 5)) * 9 + tap) * 3072 + (ci & 31) * 96 + co] = tf32r(v);
        }
    }
}

// ---------------- init: DCT-II matrices ----------------
__global__ void k_init_dct() {
    int t = blockIdx.x * blockDim.x + threadIdx.x;
    int k = t >> 7, i = t & 127;
    float arg = (float)((2 * i + 1) * k) * (1.0f / 256.0f);
    float v = cospif(arg) * 0.125f;
    if (k == 0) v *= 0.70710678118654752440f;
    g_Dt[k * 128 + i] = v;      // D[freq k][pos i]
    g_DT[i * 128 + k] = v;      // D^T[pos i][freq k]
}

// ---------------- prep: Wcomb dup, bcomb, MLP tf32 transposes ----------------
__global__ void k_prep2(const float* __restrict__ qkv_w, const float* __restrict__ qkv_b,
                        const float* __restrict__ proj_w, const float* __restrict__ proj_b,
                        const float* __restrict__ w1, const float* __restrict__ w2) {
    int blk = blockIdx.x, tid = threadIdx.x;
    if (blk < 96) {
        if (tid < 96) {
            float s = 0.f;
            for (int m = 0; m < 96; m++)
                s += proj_w[blk * 96 + m] * qkv_w[(192 + m) * 96 + tid];
            g_WcombP[tid * 96 + blk] = pk2(s, s);
        }
    } else if (blk == 96) {
        if (tid < 96) {
            float s = proj_b[tid];
            for (int m = 0; m < 96; m++)
                s += proj_w[tid * 96 + m] * qkv_b[192 + m];
            g_bcomb[tid] = s;
        }
    } else {
        int t = (blk - 97) * 256 + tid;
        if (t < 96 * 384) {
            { int k = t / 384, j = t % 384; g_W1t[t] = tf32r(w1[j * 96 + k]); }
            { int k = t / 96,  i = t % 96;  g_W2t[t] = tf32r(w2[i * 384 + k]); }
        }
    }
}

// ---------------- tensor-core conv via mma.sync tf32 (proven R14 version) ----------------
#define A_PLANE (130*36)
#define SM_A_FLOATS (3*A_PLANE)
#define SMEM_CONV ((SM_A_FLOATS + 32*100) * 4)       // 68960
__global__ void __launch_bounds__(256, 2)
k_conv() {
    extern __shared__ float smf[];
    float* As = smf;
    float* Bs = smf + SM_A_FLOATS;
    int tid = threadIdx.x;
    int y = blockIdx.x, b = blockIdx.y;
    int lane = tid & 31, wid = tid >> 5;
    int grp = lane >> 2, qid = lane & 3;
    int m_base = (wid >> 1) * 32;
    int n_base = (wid & 1) * 48;

    float acc[2][6][4];
#pragma unroll
    for (int mt = 0; mt < 2; mt++)
#pragma unroll
        for (int nt = 0; nt < 6; nt++)
#pragma unroll
            for (int q = 0; q < 4; q++) acc[mt][nt][q] = 0.f;

    for (int s = 0; s < 6; s++) {
        int img = s / 3, kblk = s % 3;
        {
            const float* base = (img ? g_xT2 : g_xT1) + (size_t)b * HWp * 96 + kblk * 32;
            for (int idx = tid; idx < 3120; idx += 256) {
                int r = idx >> 3, c4 = idx & 7;
                int dy = r / 130, pxi = r % 130;
                int x = pxi - 1;
                int yy = y + dy - 1;
                bool ok = (x >= 0) && (x < 128) && (yy >= 0) && (yy < 128);
                const float* src = base + (size_t)((ok ? yy : 0) * 128 + (ok ? x : 0)) * 96 + c4 * 4;
                cp16(smem_u32(As + dy * A_PLANE + pxi * 36 + c4 * 4), src, ok ? 16 : 0);
            }
        }
        for (int tap = 0; tap < 9; tap++) {
            {
                const float* wsrc = g_wT + (size_t)((img * 3 + kblk) * 9 + tap) * 3072;
                for (int idx = tid; idx < 768; idx += 256) {
                    int k = idx / 24, ch = idx % 24;
                    cp16(smem_u32(Bs + k * 100 + ch * 4), wsrc + k * 96 + ch * 4, 16);
                }
            }
            CP_COMMIT();
            CP_WAIT0();
            __syncthreads();
            int dy = tap / 3, dx = tap % 3 - 1;
            const float* Ap = As + dy * A_PLANE;
#pragma unroll
            for (int kk = 0; kk < 4; kk++) {
                int k0 = kk * 8;
                float a[2][4];
#pragma unroll
                for (int mt = 0; mt < 2; mt++) {
                    int m0 = m_base + mt * 16 + grp + dx + 1;
                    a[mt][0] = Ap[m0 * 36 + k0 + qid];
                    a[mt][1] = Ap[(m0 + 8) * 36 + k0 + qid];
                    a[mt][2] = Ap[m0 * 36 + k0 + qid + 4];
                    a[mt][3] = Ap[(m0 + 8) * 36 + k0 + qid + 4];
                }
#pragma unroll
                for (int nt = 0; nt < 6; nt++) {
                    int nc = n_base + nt * 8 + grp;
                    float b0 = Bs[(k0 + qid) * 100 + nc];
                    float b1 = Bs[(k0 + qid + 4) * 100 + nc];
                    mma816(acc[0][nt], a[0], b0, b1);
                    mma816(acc[1][nt], a[1], b0, b1);
                }
            }
            __syncthreads();
        }
    }

    size_t tokbase = (size_t)b * HWp + (size_t)y * 128;
#pragma unroll
    for (int mt = 0; mt < 2; mt++) {
#pragma unroll
        for (int half = 0; half < 2; half++) {
            int m = m_base + mt * 16 + grp + half * 8;
            float* dst = g_tokA + (tokbase + m) * 96;
            const float* xs = g_xsum + (tokbase + m) * 96;
#pragma unroll
            for (int nt = 0; nt < 6; nt++) {
                int co = n_base + nt * 8 + 2 * qid;
                float2 sv = *(const float2*)(xs + co);
                float2 o;
                o.x = acc[mt][nt][half * 2 + 0] + sv.x;
                o.y = acc[mt][nt][half * 2 + 1] + sv.y;
                *(float2*)(dst + co) = o;
            }
        }
    }
}

// ---------------- swin attention (folded), smem-staged weights (unchanged) ----------------
__global__ void __launch_bounds__(256)
k_attn(const float* __restrict__ g1, const float* __restrict__ b1) {
    extern __shared__ __align__(16) ull dynsm[];
    ull*   wsm = dynsm;
    float* tns = (float*)(dynsm + 9216);
    int tid = threadIdx.x;
    int warp = tid >> 5, lane = tid & 31;
    int tokbase = blockIdx.x * 64 + warp * 8;
    float* tnw = tns + warp * 960;

#pragma unroll
    for (int i = 0; i < 18; i++) {
        int idx = tid + i * 256;
        cp16(smem_u32(wsm + 2 * idx), g_WcombP + 2 * idx, 16);
    }
    CP_COMMIT();

    float tv[8][3];
#pragma unroll
    for (int t = 0; t < 8; t++) {
        const float* tp = g_tokA + (size_t)(tokbase + t) * 96;
        float a = tp[lane], bb = tp[lane + 32], cc = tp[lane + 64];
        tv[t][0] = a; tv[t][1] = bb; tv[t][2] = cc;
        float s = a + bb + cc;
#pragma unroll
        for (int o = 16; o; o >>= 1) s += __shfl_xor_sync(0xffffffff, s, o);
        float m = s * (1.f / 96.f);
        float d0 = a - m, d1 = bb - m, d2 = cc - m;
        float q = d0 * d0 + d1 * d1 + d2 * d2;
#pragma unroll
        for (int o = 16; o; o >>= 1) q += __shfl_xor_sync(0xffffffff, q, o);
        float rstd = rsqrtf(q * (1.f / 96.f) + 1e-5f);
        tnw[lane * 10 + t]        = d0 * rstd * g1[lane]      + b1[lane];
        tnw[(lane + 32) * 10 + t] = d1 * rstd * g1[lane + 32] + b1[lane + 32];
        tnw[(lane + 64) * 10 + t] = d2 * rstd * g1[lane + 64] + b1[lane + 64];
    }
    CP_WAIT0();
    __syncthreads();

    ull acc[4][3];
#pragma unroll
    for (int p = 0; p < 4; p++) { acc[p][0] = 0; acc[p][1] = 0; acc[p][2] = 0; }
#pragma unroll 4
    for (int k = 0; k < 96; k++) {
        ull W0 = wsm[k * 96 + lane];
        ull W1 = wsm[k * 96 + lane + 32];
        ull W2 = wsm[k * 96 + lane + 64];
#pragma unroll
        for (int p = 0; p < 4; p++) {
            ull sp = *(const ull*)&tnw[k * 10 + 2 * p];
            ffma2(acc[p][0], sp, W0);
            ffma2(acc[p][1], sp, W1);
            ffma2(acc[p][2], sp, W2);
        }
    }
#pragma unroll
    for (int p = 0; p < 4; p++) {
#pragma unroll
        for (int c = 0; c < 3; c++) {
            float o0, o1; upk(acc[p][c], o0, o1);
            int ch = lane + 32 * c;
            g_tokB[(size_t)(tokbase + 2 * p) * 96 + ch]     = tv[2 * p][c]     + o0 + g_bcomb[ch];
            g_tokB[(size_t)(tokbase + 2 * p + 1) * 96 + ch] = tv[2 * p + 1][c] + o1 + g_bcomb[ch];
        }
    }
}

// ---------------- swin MLP via mma.sync tf32 ----------------
// 128 tokens/CTA, 8 warps (16 tok each). 4 chunks of N=96:
// GEMM1 chunk -> gelu -> gS ; O += gS @ W2chunk (persistent regs).
#define MLP_SMEM ((12800 + 9600 + 12800) * 4)    // 140800 B
__global__ void __launch_bounds__(256, 1)
k_mlp(const float* __restrict__ g2, const float* __restrict__ b2,
      const float* __restrict__ mb1, const float* __restrict__ mb2) {
    extern __shared__ float smf[];
    float* tnS = smf;            // [128][100]
    float* wS  = smf + 12800;    // [96][100]
    float* gS  = smf + 22400;    // [128][100]
    int tid = threadIdx.x;
    int warp = tid >> 5, lane = tid & 31;
    int grp = lane >> 2, qid = lane & 3;
    int tokbase = blockIdx.x * 128;

    // LN prologue: 16 tokens per warp
    for (int t = 0; t < 16; t++) {
        int tok = warp * 16 + t;
        const float* tp = g_tokB + (size_t)(tokbase + tok) * 96;
        float a = tp[lane], bb = tp[lane + 32], cc = tp[lane + 64];
        float s = a + bb + cc;
#pragma unroll
        for (int o = 16; o; o >>= 1) s += __shfl_xor_sync(0xffffffff, s, o);
        float m = s * (1.f / 96.f);
        float d0 = a - m, d1 = bb - m, d2 = cc - m;
        float q = d0 * d0 + d1 * d1 + d2 * d2;
#pragma unroll
        for (int o = 16; o; o >>= 1) q += __shfl_xor_sync(0xffffffff, q, o);
        float rstd = rsqrtf(q * (1.f / 96.f) + 1e-5f);
        tnS[tok * 100 + lane]      = d0 * rstd * g2[lane]      + b2[lane];
        tnS[tok * 100 + lane + 32] = d1 * rstd * g2[lane + 32] + b2[lane + 32];
        tnS[tok * 100 + lane + 64] = d2 * rstd * g2[lane + 64] + b2[lane + 64];
    }
    __syncthreads();

    int m0 = warp * 16 + grp;
    float acc2[12][4];
#pragma unroll
    for (int nt = 0; nt < 12; nt++)
#pragma unroll
        for (int q = 0; q < 4; q++) acc2[nt][q] = 0.f;

    for (int c = 0; c < 4; c++) {
        // stage W1 chunk [96 k][96 n]
        for (int idx = tid; idx < 2304; idx += 256) {
            int k = idx / 24, ch = idx % 24;
            cp16(smem_u32(wS + k * 100 + ch * 4), g_W1t + k * 384 + c * 96 + ch * 4, 16);
        }
        CP_COMMIT();
        CP_WAIT0();
        __syncthreads();

        float acc1[12][4];
#pragma unroll
        for (int nt = 0; nt < 12; nt++)
#pragma unroll
            for (int q = 0; q < 4; q++) acc1[nt][q] = 0.f;
#pragma unroll
        for (int k0t = 0; k0t < 12; k0t++) {
            int k0 = k0t * 8;
            float a[4];
            a[0] = tnS[m0 * 100 + k0 + qid];
            a[1] = tnS[(m0 + 8) * 100 + k0 + qid];
            a[2] = tnS[m0 * 100 + k0 + qid + 4];
            a[3] = tnS[(m0 + 8) * 100 + k0 + qid + 4];
#pragma unroll
            for (int nt = 0; nt < 12; nt++) {
                int nc = nt * 8 + grp;
                float b0 = wS[(k0 + qid) * 100 + nc];
                float b1 = wS[(k0 + qid + 4) * 100 + nc];
                mma816(acc1[nt], a, b0, b1);
            }
        }
        __syncthreads();   // all reads of wS (W1) done

        // stage W2 chunk [96 k][96 co] (overwrite wS)
        for (int idx = tid; idx < 2304; idx += 256) {
            int k = idx / 24, ch = idx % 24;
            cp16(smem_u32(wS + k * 100 + ch * 4), g_W2t + (size_t)(c * 96 + k) * 96 + ch * 4, 16);
        }
        CP_COMMIT();
        CP_WAIT0();

        // gelu -> gS (each warp writes/reads only its own token rows)
#pragma unroll
        for (int nt = 0; nt < 12; nt++)
#pragma unroll
            for (int half = 0; half < 2; half++)
#pragma unroll
                for (int pc = 0; pc < 2; pc++) {
                    int j = nt * 8 + 2 * qid + pc;
                    int row = warp * 16 + grp + 8 * half;
                    float x = acc1[nt][half * 2 + pc] + mb1[c * 96 + j];
                    gS[row * 100 + j] = gelu_ex(x);
                }
        __syncthreads();   // W2 staged by all threads, gS not cross-warp anyway

#pragma unroll
        for (int k0t = 0; k0t < 12; k0t++) {
            int k0 = k0t * 8;
            float a[4];
            a[0] = gS[m0 * 100 + k0 + qid];
            a[1] = gS[(m0 + 8) * 100 + k0 + qid];
            a[2] = gS[m0 * 100 + k0 + qid + 4];
            a[3] = gS[(m0 + 8) * 100 + k0 + qid + 4];
#pragma unroll
            for (int nt = 0; nt < 12; nt++) {
                int nc = nt * 8 + grp;
                float b0 = wS[(k0 + qid) * 100 + nc];
                float b1 = wS[(k0 + qid + 4) * 100 + nc];
                mma816(acc2[nt], a, b0, b1);
            }
        }
        __syncthreads();   // before next chunk overwrites wS
    }

    // epilogue: out = t + O + mb2, token-major
#pragma unroll
    for (int half = 0; half < 2; half++) {
        int row = warp * 16 + grp + 8 * half;
        size_t tok = (size_t)(tokbase + row);
        const float* tsrc = g_tokB + tok * 96;
        float* dst = g_tokA + tok * 96;
#pragma unroll
        for (int nt = 0; nt < 12; nt++)
#pragma unroll
            for (int pc = 0; pc < 2; pc++) {
                int co = nt * 8 + 2 * qid + pc;
                dst[co] = tsrc[co] + acc2[nt][half * 2 + pc] + mb2[co];
            }
    }
}

// ---------------- transpose token-major -> CHW ----------------
__global__ void k_t2() {
    __shared__ float tile[32][33];
    int b = blockIdx.z, c0 = blockIdx.y * 32, p0 = blockIdx.x * 32;
    int tx = threadIdx.x, ty0 = threadIdx.y;
    for (int yy = ty0; yy < 32; yy += 8)
        tile[yy][tx] = g_tokA[(size_t)(b * HWp + p0 + yy) * 96 + c0 + tx];
    __syncthreads();
    for (int yy = ty0; yy < 32; yy += 8)
        g_cross[(size_t)(b * 96 + c0 + yy) * HWp + p0 + tx] = tile[tx][yy];
}

// ---------------- 2D DCT via mma.sync tf32 ----------------
// Z = D @ X @ D^T per (b,c). M1 holds D then D^T. stride 132.
#define DCT_SMEM ((3 * 128 * 132) * 4)    // 202752 B
__global__ void __launch_bounds__(256, 1)
k_dct() {
    extern __shared__ float smf[];
    float* M1 = smf;               // [128][132]
    float* Xs = smf + 16896;       // [128][132]
    float* Ys = smf + 33792;       // [128][132]
    int tid = threadIdx.x;
    int bc = blockIdx.x;
    int lane = tid & 31, warp = tid >> 5;
    int grp = lane >> 2, qid = lane & 3;
    int m0 = warp * 16 + grp;

    const float* Xsrc = g_cross + (size_t)bc * HWp;
    for (int idx = tid; idx < 4096; idx += 256) {
        int r = idx >> 5, ch = idx & 31;
        cp16(smem_u32(M1 + r * 132 + ch * 4), g_Dt + r * 128 + ch * 4, 16);
        cp16(smem_u32(Xs + r * 132 + ch * 4), Xsrc + r * 128 + ch * 4, 16);
    }
    CP_COMMIT();
    CP_WAIT0();
    __syncthreads();

    // stage 1: Y = D @ X
    {
        float acc[16][4];
#pragma unroll
        for (int nt = 0; nt < 16; nt++)
#pragma unroll
            for (int q = 0; q < 4; q++) acc[nt][q] = 0.f;
        for (int k0t = 0; k0t < 16; k0t++) {
            int k0 = k0t * 8;
            float a[4];
            a[0] = M1[m0 * 132 + k0 + qid];
            a[1] = M1[(m0 + 8) * 132 + k0 + qid];
            a[2] = M1[m0 * 132 + k0 + qid + 4];
            a[3] = M1[(m0 + 8) * 132 + k0 + qid + 4];
#pragma unroll
            for (int nt = 0; nt < 16; nt++) {
                int nc = nt * 8 + grp;
                float b0 = Xs[(k0 + qid) * 132 + nc];
                float b1 = Xs[(k0 + qid + 4) * 132 + nc];
                mma816(acc[nt], a, b0, b1);
            }
        }
#pragma unroll
        for (int nt = 0; nt < 16; nt++)
#pragma unroll
            for (int half = 0; half < 2; half++)
#pragma unroll
                for (int pc = 0; pc < 2; pc++)
                    Ys[(m0 + 8 * half) * 132 + nt * 8 + 2 * qid + pc] = acc[nt][half * 2 + pc];
    }
    __syncthreads();   // M1 reads done

    // stage D^T into M1
    for (int idx = tid; idx < 4096; idx += 256) {
        int r = idx >> 5, ch = idx & 31;
        cp16(smem_u32(M1 + r * 132 + ch * 4), g_DT + r * 128 + ch * 4, 16);
    }
    CP_COMMIT();
    CP_WAIT0();
    __syncthreads();

    // stage 2: Z = Y @ D^T
    {
        float acc[16][4];
#pragma unroll
        for (int nt = 0; nt < 16; nt++)
#pragma unroll
            for (int q = 0; q < 4; q++) acc[nt][q] = 0.f;
        for (int k0t = 0; k0t < 16; k0t++) {
            int k0 = k0t * 8;
            float a[4];
            a[0] = Ys[m0 * 132 + k0 + qid];
            a[1] = Ys[(m0 + 8) * 132 + k0 + qid];
            a[2] = Ys[m0 * 132 + k0 + qid + 4];
            a[3] = Ys[(m0 + 8) * 132 + k0 + qid + 4];
#pragma unroll
            for (int nt = 0; nt < 16; nt++) {
                int nc = nt * 8 + grp;
                float b0 = M1[(k0 + qid) * 132 + nc];
                float b1 = M1[(k0 + qid + 4) * 132 + nc];
                mma816(acc[nt], a, b0, b1);
            }
        }
        float* dst = g_dct + (size_t)bc * HWp;
#pragma unroll
        for (int nt = 0; nt < 16; nt++)
#pragma unroll
            for (int half = 0; half < 2; half++)
#pragma unroll
                for (int pc = 0; pc < 2; pc++)
                    dst[(m0 + 8 * half) * 128 + nt * 8 + 2 * qid + pc] = acc[nt][half * 2 + pc];
    }
}

// ---------------- channel-mean |dct| ----------------
__global__ void k_energy() {
    int g = blockIdx.x * blockDim.x + threadIdx.x;
    int b = g >> 12, p4 = g & 4095;
    const float4* base = (const float4*)(g_dct + (size_t)b * 96 * HWp) + p4;
    float4 s = make_float4(0.f, 0.f, 0.f, 0.f);
    for (int c = 0; c < 96; c++) {
        float4 v = base[(size_t)c * 4096];
        s.x += fabsf(v.x); s.y += fabsf(v.y); s.z += fabsf(v.z); s.w += fabsf(v.w);
    }
    float inv = 1.f / 96.f;
    s.x *= inv; s.y *= inv; s.z *= inv; s.w *= inv;
    ((float4*)(g_energy + b * HWp))[p4] = s;
}

// ---------------- top-96 via histogram threshold + rank sort ----------------
__global__ void __launch_bounds__(256)
k_topk(const float* __restrict__ fw1, const float* __restrict__ fb1,
       const float* __restrict__ fw2, const float* __restrict__ fb2) {
    extern __shared__ float e[];
    int* hist = (int*)(e + 16384);
    __shared__ int csum[256];
    __shared__ int s_T, s_cnt;
    __shared__ float tk[96];
    __shared__ float hh[24];
    int b = blockIdx.x, tid = threadIdx.x;

    const float4* src = (const float4*)(g_energy + b * HWp);
    float4* e4 = (float4*)e;
    for (int l = tid; l < 4096; l += 256) e4[l] = src[l];
    for (int l = tid; l < 4096; l += 256) hist[l] = 0;
    __syncthreads();
    for (int l = tid; l < 16384; l += 256) {
        int key = (int)(__float_as_uint(e[l]) >> 19);
        atomicAdd(&hist[key], 1);
    }
    __syncthreads();
    {
        int s = 0;
#pragma unroll
        for (int k = 0; k < 16; k++) s += hist[tid * 16 + k];
        csum[tid] = s;
    }
    __syncthreads();
    if (tid == 0) {
        int run = 0, cstar = 0;
        for (int c = 255; c >= 0; c--) {
            if (run + csum[c] >= 96) { cstar = c; break; }
            run += csum[c];
        }
        int T = cstar * 16;
        for (int k = 15; k >= 0; k--) {
            int bin = cstar * 16 + k;
            if (run + hist[bin] >= 96) { T = bin; break; }
            run += hist[bin];
        }
        s_T = T; s_cnt = 0;
    }
    __syncthreads();
    int T = s_T;
    float* cand = (float*)hist;
    __syncthreads();
    for (int l = tid; l < 16384; l += 256) {
        float v = e[l];
        if ((int)(__float_as_uint(v) >> 19) >= T) {
            int pos = atomicAdd(&s_cnt, 1);
            if (pos < 4096) cand[pos] = v;
        }
    }
    __syncthreads();
    int M = s_cnt; if (M > 4096) M = 4096;
    for (int i = tid; i < M; i += 256) {
        float v = cand[i];
        int r = 0;
        for (int j = 0; j < M; j++) {
            float u = cand[j];
            r += (u > v) || (u == v && j < i);
        }
        if (r < 96) tk[r] = v;
    }
    __syncthreads();
    if (tid < 24) {
        float s = fb1[tid];
        for (int k = 0; k < 96; k++) s += tk[k] * fw1[tid * 96 + k];
        hh[tid] = fmaxf(s, 0.f);
    }
    __syncthreads();
    if (tid == 0) {
        float a = fb2[0];
        for (int j = 0; j < 24; j++) a += hh[j] * fw2[j];
        g_scale[b] = 1.f + 1.f / (1.f + expf(-a));
    }
}

// ---------------- epilogue ----------------
__global__ void k_final(const float* __restrict__ x1, const float* __restrict__ x2,
                        float* __restrict__ out) {
    int i = blockIdx.x * blockDim.x + threadIdx.x;
    float s = g_scale[i / (96 * HWp / 4)];
    float4 c = ((const float4*)g_cross)[i];
    float4 a = ((const float4*)x1)[i];
    float4 b = ((const float4*)x2)[i];
    float4 o1, o2;
    o1.x = a.x + s * c.x; o1.y = a.y + s * c.y; o1.z = a.z + s * c.z; o1.w = a.w + s * c.w;
    o2.x = b.x + s * c.x; o2.y = b.y + s * c.y; o2.z = b.z + s * c.z; o2.w = b.w + s * c.w;
    ((float4*)out)[i]            = o1;
    ((float4*)out)[NTOT / 4 + i] = o2;
}

extern "C" void kernel_launch(void* const* d_in, const int* in_sizes, int n_in,
                              void* d_out, int out_size) {
    const float* x1     = (const float*)d_in[0];
    const float* x2     = (const float*)d_in[1];
    const float* w_tx1  = (const float*)d_in[2];
    const float* lm1    = (const float*)d_in[3];
    const float* theta1 = (const float*)d_in[4];
    const float* w_tx2  = (const float*)d_in[5];
    const float* lm2    = (const float*)d_in[6];
    const float* theta2 = (const float*)d_in[7];
    const float* ln1_g  = (const float*)d_in[8];
    const float* ln1_b  = (const float*)d_in[9];
    const float* qkv_w  = (const float*)d_in[10];
    const float* qkv_b  = (const float*)d_in[11];
    const float* proj_w = (const float*)d_in[12];
    const float* proj_b = (const float*)d_in[13];
    const float* ln2_g  = (const float*)d_in[14];
    const float* ln2_b  = (const float*)d_in[15];
    const float* mlp_w1 = (const float*)d_in[16];
    const float* mlp_b1 = (const float*)d_in[17];
    const float* mlp_w2 = (const float*)d_in[18];
    const float* mlp_b2 = (const float*)d_in[19];
    const float* fc_w1  = (const float*)d_in[20];
    const float* fc_b1  = (const float*)d_in[21];
    const float* fc_w2  = (const float*)d_in[22];
    const float* fc_b2  = (const float*)d_in[23];
    float* out = (float*)d_out;

    cudaFuncSetAttribute(k_conv, cudaFuncAttributeMaxDynamicSharedMemorySize, SMEM_CONV);
    cudaFuncSetAttribute(k_attn, cudaFuncAttributeMaxDynamicSharedMemorySize, 104448);
    cudaFuncSetAttribute(k_mlp,  cudaFuncAttributeMaxDynamicSharedMemorySize, MLP_SMEM);
    cudaFuncSetAttribute(k_dct,  cudaFuncAttributeMaxDynamicSharedMemorySize, DCT_SMEM);
    cudaFuncSetAttribute(k_topk, cudaFuncAttributeMaxDynamicSharedMemorySize, 81920);

    // slot 4 (ncu capture) = k_conv
    k_xT<<<dim3(512, 3, 4), dim3(32, 8)>>>(x1, x2);
    k_wprep<<<36, 256>>>(w_tx1, lm1, theta1, w_tx2, lm2, theta2);
    k_prep2<<<241, 256>>>(qkv_w, qkv_b, proj_w, proj_b, mlp_w1, mlp_w2);
    k_conv<<<dim3(128, 4), 256, SMEM_CONV>>>();
    k_attn<<<1024, 256, 104448>>>(ln1_g, ln1_b);
    k_mlp<<<512, 256, MLP_SMEM>>>(ln2_g, ln2_b, mlp_b1, mlp_b2);
    k_init_dct<<<64, 256>>>();
    k_t2<<<dim3(512, 3, 4), dim3(32, 8)>>>();
    k_dct<<<384, 256, DCT_SMEM>>>();
    k_energy<<<64, 256>>>();
    k_topk<<<4, 256, 81920>>>(fc_w1, fc_b1, fc_w2, fc_b2);
    k_final<<<NTOT / 4 / 256, 256>>>(x1, x2, out);
}

// round 16
// speedup vs baseline: 2.9752x; 1.0277x over previous
#include <cuda_runtime.h>
#include <math.h>
#include <stdint.h>

#define Bq   4
#define Cc   96
#define HWp  16384
#define NTOT (Bq*Cc*HWp)

typedef unsigned long long ull;

__device__ __forceinline__ float gelu_ex(float x) {
    return 0.5f * x * (1.f + erff(x * 0.70710678118654752f));
}
__device__ __forceinline__ float tf32r(float x) {
    uint32_t r; asm("cvt.rna.tf32.f32 %0,%1;" : "=r"(r) : "f"(x));
    return __uint_as_float(r);
}
__device__ __forceinline__ unsigned smem_u32(const void* p) {
    return (unsigned)__cvta_generic_to_shared(p);
}
__device__ __forceinline__ void cp16(unsigned dst, const void* src, int n) {
    asm volatile("cp.async.cg.shared.global [%0],[%1],16,%2;" :: "r"(dst), "l"(src), "r"(n));
}
#define CP_COMMIT() asm volatile("cp.async.commit_group;")
#define CP_WAIT0()  asm volatile("cp.async.wait_group 0;")

// warp-level tf32 MMA, base-ISA
__device__ __forceinline__ void mma816(float* c, const float* a, float b0, float b1) {
    asm volatile("mma.sync.aligned.m16n8k8.row.col.f32.tf32.tf32.f32 "
        "{%0,%1,%2,%3},{%4,%5,%6,%7},{%8,%9},{%0,%1,%2,%3};"
        : "+f"(c[0]), "+f"(c[1]), "+f"(c[2]), "+f"(c[3])
        : "r"(__float_as_uint(a[0])), "r"(__float_as_uint(a[1])),
          "r"(__float_as_uint(a[2])), "r"(__float_as_uint(a[3])),
          "r"(__float_as_uint(b0)), "r"(__float_as_uint(b1)));
}

// ---------------- device scratch ----------------
__device__ float g_xT1[NTOT];       // token-major tf32(x1)
__device__ float g_xT2[NTOT];       // token-major tf32(x2)
__device__ float g_xsum[NTOT];      // token-major 2*(x1+x2), fp32 exact
__device__ float g_wT[2*3*9*3072];  // conv B tiles [img][kblk][tap][ci32][co96], tf32
__device__ float g_Dt[128*128];     // D row-major [freq][pos]
__device__ float g_DT[128*128];     // D^T row-major [pos][freq]
__device__ float g_Wct[96*96];      // attn B tile [k][co], tf32
__device__ float g_bcomb[96];
__device__ float g_W1t[96*384];     // [k][j] tf32
__device__ float g_W2t[384*96];     // [k][co] tf32
__device__ float g_tokA[NTOT];
__device__ float g_tokB[NTOT];
__device__ float g_cross[NTOT];
__device__ float g_dct[NTOT];
__device__ float g_energy[Bq*HWp];
__device__ float g_scale[Bq];

// ---------------- transpose CHW->token-major + tf32 + residual sum ----------------
__global__ void k_xT(const float* __restrict__ x1, const float* __restrict__ x2) {
    __shared__ float t1[32][33], t2[32][33];
    int b = blockIdx.z, c0 = blockIdx.y * 32, p0 = blockIdx.x * 32;
    int tx = threadIdx.x, ty = threadIdx.y;
    for (int yy = ty; yy < 32; yy += 8) {
        size_t idx = (size_t)(b * 96 + c0 + yy) * HWp + p0 + tx;
        t1[yy][tx] = x1[idx]; t2[yy][tx] = x2[idx];
    }
    __syncthreads();
    for (int yy = ty; yy < 32; yy += 8) {
        size_t o = (size_t)(b * HWp + p0 + yy) * 96 + c0 + tx;
        float a = t1[tx][yy], bb = t2[tx][yy];
        g_xT1[o] = tf32r(a);
        g_xT2[o] = tf32r(bb);
        g_xsum[o] = 2.f * (a + bb);
    }
}

// ---------------- LDC effective weights -> conv B tiles, tf32 ----------------
__global__ void k_wprep(const float* __restrict__ w1, const float* __restrict__ lm1,
                        const float* __restrict__ th1,
                        const float* __restrict__ w2, const float* __restrict__ lm2,
                        const float* __restrict__ th2) {
    int t = blockIdx.x * 256 + threadIdx.x;
    if (t >= 96 * 96) return;
    int co = t / 96, ci = t % 96;
#pragma unroll
    for (int img = 0; img < 2; img++) {
        const float* ws = (img ? w2 : w1) + t * 9;
        const float* lm = img ? lm2 : lm1;
        float theta = img ? th2[0] : th1[0];
        float s = 0.f;
#pragma unroll
        for (int k = 0; k < 9; k++) s += ws[k];
        float sc = 1.f - theta * lm[t] * s;
#pragma unroll
        for (int tap = 0; tap < 9; tap++) {
            float v = ws[tap];
            if (tap == 4) v *= sc;
            g_wT[(size_t)((img * 3 + (ci >> 5)) * 9 + tap) * 3072 + (ci & 31) * 96 + co] = tf32r(v);
        }
    }
}

// ---------------- init: DCT-II matrices ----------------
__global__ void k_init_dct() {
    int t = blockIdx.x * blockDim.x + threadIdx.x;
    int k = t >> 7, i = t & 127;
    float arg = (float)((2 * i + 1) * k) * (1.0f / 256.0f);
    float v = cospif(arg) * 0.125f;
    if (k == 0) v *= 0.70710678118654752440f;
    g_Dt[k * 128 + i] = v;
    g_DT[i * 128 + k] = v;
}

// ---------------- prep: Wcomb tf32, bcomb, MLP tf32 transposes ----------------
__global__ void k_prep2(const float* __restrict__ qkv_w, const float* __restrict__ qkv_b,
                        const float* __restrict__ proj_w, const float* __restrict__ proj_b,
                        const float* __restrict__ w1, const float* __restrict__ w2) {
    int blk = blockIdx.x, tid = threadIdx.x;
    if (blk < 96) {
        if (tid < 96) {
            float s = 0.f;
            for (int m = 0; m < 96; m++)
                s += proj_w[blk * 96 + m] * qkv_w[(192 + m) * 96 + tid];
            g_Wct[tid * 96 + blk] = tf32r(s);   // [k=tid][co=blk]
        }
    } else if (blk == 96) {
        if (tid < 96) {
            float s = proj_b[tid];
            for (int m = 0; m < 96; m++)
                s += proj_w[tid * 96 + m] * qkv_b[192 + m];
            g_bcomb[tid] = s;
        }
    } else {
        int t = (blk - 97) * 256 + tid;
        if (t < 96 * 384) {
            { int k = t / 384, j = t % 384; g_W1t[t] = tf32r(w1[j * 96 + k]); }
            { int k = t / 96,  i = t % 96;  g_W2t[t] = tf32r(w2[i * 384 + k]); }
        }
    }
}

// ---------------- tensor-core conv, 3-tap B batches ----------------
#define A_PLANE (130*36)
#define SM_A_FLOATS (3*A_PLANE)                         // 14040
#define SMEM_CONV ((SM_A_FLOATS + 3*3200) * 4)          // 94560
__global__ void __launch_bounds__(256, 2)
k_conv() {
    extern __shared__ float smf[];
    float* As = smf;
    float* Bs = smf + SM_A_FLOATS;                      // [3][32][100]
    int tid = threadIdx.x;
    int y = blockIdx.x, b = blockIdx.y;
    int lane = tid & 31, wid = tid >> 5;
    int grp = lane >> 2, qid = lane & 3;
    int m_base = (wid >> 1) * 32;
    int n_base = (wid & 1) * 48;

    float acc[2][6][4];
#pragma unroll
    for (int mt = 0; mt < 2; mt++)
#pragma unroll
        for (int nt = 0; nt < 6; nt++)
#pragma unroll
            for (int q = 0; q < 4; q++) acc[mt][nt][q] = 0.f;

    for (int s = 0; s < 6; s++) {
        int img = s / 3, kblk = s % 3;
        // issue A plane (uncommitted; joins first B group's commit)
        {
            const float* base = (img ? g_xT2 : g_xT1) + (size_t)b * HWp * 96 + kblk * 32;
            for (int idx = tid; idx < 3120; idx += 256) {
                int r = idx >> 3, c4 = idx & 7;
                int dy = r / 130, pxi = r % 130;
                int x = pxi - 1;
                int yy = y + dy - 1;
                bool ok = (x >= 0) && (x < 128) && (yy >= 0) && (yy < 128);
                const float* src = base + (size_t)((ok ? yy : 0) * 128 + (ok ? x : 0)) * 96 + c4 * 4;
                cp16(smem_u32(As + dy * A_PLANE + pxi * 36 + c4 * 4), src, ok ? 16 : 0);
            }
        }
        for (int tg = 0; tg < 3; tg++) {
            // stage B for taps tg*3 .. tg*3+2
            {
                const float* wbase = g_wT + (size_t)((img * 3 + kblk) * 9 + tg * 3) * 3072;
                for (int idx = tid; idx < 2304; idx += 256) {
                    int t3 = idx / 768, rem = idx % 768;
                    int k = rem / 24, ch = rem % 24;
                    cp16(smem_u32(Bs + t3 * 3200 + k * 100 + ch * 4),
                         wbase + t3 * 3072 + k * 96 + ch * 4, 16);
                }
            }
            CP_COMMIT();
            CP_WAIT0();
            __syncthreads();
#pragma unroll
            for (int t3 = 0; t3 < 3; t3++) {
                int tap = tg * 3 + t3;
                int dy = tap / 3, dx = tap % 3 - 1;
                const float* Ap = As + dy * A_PLANE;
                const float* Bp = Bs + t3 * 3200;
#pragma unroll
                for (int kk = 0; kk < 4; kk++) {
                    int k0 = kk * 8;
                    float a[2][4];
#pragma unroll
                    for (int mt = 0; mt < 2; mt++) {
                        int m0 = m_base + mt * 16 + grp + dx + 1;
                        a[mt][0] = Ap[m0 * 36 + k0 + qid];
                        a[mt][1] = Ap[(m0 + 8) * 36 + k0 + qid];
                        a[mt][2] = Ap[m0 * 36 + k0 + qid + 4];
                        a[mt][3] = Ap[(m0 + 8) * 36 + k0 + qid + 4];
                    }
#pragma unroll
                    for (int nt = 0; nt < 6; nt++) {
                        int nc = n_base + nt * 8 + grp;
                        float b0 = Bp[(k0 + qid) * 100 + nc];
                        float b1 = Bp[(k0 + qid + 4) * 100 + nc];
                        mma816(acc[0][nt], a[0], b0, b1);
                        mma816(acc[1][nt], a[1], b0, b1);
                    }
                }
            }
            __syncthreads();
        }
    }

    size_t tokbase = (size_t)b * HWp + (size_t)y * 128;
#pragma unroll
    for (int mt = 0; mt < 2; mt++) {
#pragma unroll
        for (int half = 0; half < 2; half++) {
            int m = m_base + mt * 16 + grp + half * 8;
            float* dst = g_tokA + (tokbase + m) * 96;
            const float* xs = g_xsum + (tokbase + m) * 96;
#pragma unroll
            for (int nt = 0; nt < 6; nt++) {
                int co = n_base + nt * 8 + 2 * qid;
                float2 sv = *(const float2*)(xs + co);
                float2 o;
                o.x = acc[mt][nt][half * 2 + 0] + sv.x;
                o.y = acc[mt][nt][half * 2 + 1] + sv.y;
                *(float2*)(dst + co) = o;
            }
        }
    }
}

// ---------------- swin attention via mma.sync tf32 ----------------
// out = t + LN1(t) @ Wcomb + bcomb ; 128 tokens/CTA
#define ATTN_SMEM ((12800 + 9600) * 4)   // 89600
__global__ void __launch_bounds__(256, 2)
k_attn(const float* __restrict__ g1, const float* __restrict__ b1) {
    extern __shared__ float smf[];
    float* tnS = smf;            // [128][100]
    float* wS  = smf + 12800;    // [96][100]
    int tid = threadIdx.x;
    int warp = tid >> 5, lane = tid & 31;
    int grp = lane >> 2, qid = lane & 3;
    int tokbase = blockIdx.x * 128;

    // issue weight staging first (overlaps LN prologue)
    for (int idx = tid; idx < 2304; idx += 256) {
        int k = idx / 24, ch = idx % 24;
        cp16(smem_u32(wS + k * 100 + ch * 4), g_Wct + k * 96 + ch * 4, 16);
    }
    CP_COMMIT();

    for (int t = 0; t < 16; t++) {
        int tok = warp * 16 + t;
        const float* tp = g_tokA + (size_t)(tokbase + tok) * 96;
        float a = tp[lane], bb = tp[lane + 32], cc = tp[lane + 64];
        float s = a + bb + cc;
#pragma unroll
        for (int o = 16; o; o >>= 1) s += __shfl_xor_sync(0xffffffff, s, o);
        float m = s * (1.f / 96.f);
        float d0 = a - m, d1 = bb - m, d2 = cc - m;
        float q = d0 * d0 + d1 * d1 + d2 * d2;
#pragma unroll
        for (int o = 16; o; o >>= 1) q += __shfl_xor_sync(0xffffffff, q, o);
        float rstd = rsqrtf(q * (1.f / 96.f) + 1e-5f);
        tnS[tok * 100 + lane]      = d0 * rstd * g1[lane]      + b1[lane];
        tnS[tok * 100 + lane + 32] = d1 * rstd * g1[lane + 32] + b1[lane + 32];
        tnS[tok * 100 + lane + 64] = d2 * rstd * g1[lane + 64] + b1[lane + 64];
    }
    CP_WAIT0();
    __syncthreads();

    int m0 = warp * 16 + grp;
    float acc[12][4];
#pragma unroll
    for (int nt = 0; nt < 12; nt++)
#pragma unroll
        for (int q = 0; q < 4; q++) acc[nt][q] = 0.f;
#pragma unroll
    for (int k0t = 0; k0t < 12; k0t++) {
        int k0 = k0t * 8;
        float a[4];
        a[0] = tnS[m0 * 100 + k0 + qid];
        a[1] = tnS[(m0 + 8) * 100 + k0 + qid];
        a[2] = tnS[m0 * 100 + k0 + qid + 4];
        a[3] = tnS[(m0 + 8) * 100 + k0 + qid + 4];
#pragma unroll
        for (int nt = 0; nt < 12; nt++) {
            int nc = nt * 8 + grp;
            float b0 = wS[(k0 + qid) * 100 + nc];
            float b1 = wS[(k0 + qid + 4) * 100 + nc];
            mma816(acc[nt], a, b0, b1);
        }
    }

#pragma unroll
    for (int half = 0; half < 2; half++) {
        int row = warp * 16 + grp + 8 * half;
        size_t tok = (size_t)(tokbase + row);
        const float* tsrc = g_tokA + tok * 96;
        float* dst = g_tokB + tok * 96;
#pragma unroll
        for (int nt = 0; nt < 12; nt++)
#pragma unroll
            for (int pc = 0; pc < 2; pc++) {
                int co = nt * 8 + 2 * qid + pc;
                dst[co] = tsrc[co] + acc[nt][half * 2 + pc] + g_bcomb[co];
            }
    }
}

// ---------------- swin MLP via mma.sync tf32 (proven R15) ----------------
#define MLP_SMEM ((12800 + 9600 + 12800) * 4)    // 140800 B
__global__ void __launch_bounds__(256, 1)
k_mlp(const float* __restrict__ g2, const float* __restrict__ b2,
      const float* __restrict__ mb1, const float* __restrict__ mb2) {
    extern __shared__ float smf[];
    float* tnS = smf;            // [128][100]
    float* wS  = smf + 12800;    // [96][100]
    float* gS  = smf + 22400;    // [128][100]
    int tid = threadIdx.x;
    int warp = tid >> 5, lane = tid & 31;
    int grp = lane >> 2, qid = lane & 3;
    int tokbase = blockIdx.x * 128;

    for (int t = 0; t < 16; t++) {
        int tok = warp * 16 + t;
        const float* tp = g_tokB + (size_t)(tokbase + tok) * 96;
        float a = tp[lane], bb = tp[lane + 32], cc = tp[lane + 64];
        float s = a + bb + cc;
#pragma unroll
        for (int o = 16; o; o >>= 1) s += __shfl_xor_sync(0xffffffff, s, o);
        float m = s * (1.f / 96.f);
        float d0 = a - m, d1 = bb - m, d2 = cc - m;
        float q = d0 * d0 + d1 * d1 + d2 * d2;
#pragma unroll
        for (int o = 16; o; o >>= 1) q += __shfl_xor_sync(0xffffffff, q, o);
        float rstd = rsqrtf(q * (1.f / 96.f) + 1e-5f);
        tnS[tok * 100 + lane]      = d0 * rstd * g2[lane]      + b2[lane];
        tnS[tok * 100 + lane + 32] = d1 * rstd * g2[lane + 32] + b2[lane + 32];
        tnS[tok * 100 + lane + 64] = d2 * rstd * g2[lane + 64] + b2[lane + 64];
    }
    __syncthreads();

    int m0 = warp * 16 + grp;
    float acc2[12][4];
#pragma unroll
    for (int nt = 0; nt < 12; nt++)
#pragma unroll
        for (int q = 0; q < 4; q++) acc2[nt][q] = 0.f;

    for (int c = 0; c < 4; c++) {
        for (int idx = tid; idx < 2304; idx += 256) {
            int k = idx / 24, ch = idx % 24;
            cp16(smem_u32(wS + k * 100 + ch * 4), g_W1t + k * 384 + c * 96 + ch * 4, 16);
        }
        CP_COMMIT();
        CP_WAIT0();
        __syncthreads();

        float acc1[12][4];
#pragma unroll
        for (int nt = 0; nt < 12; nt++)
#pragma unroll
            for (int q = 0; q < 4; q++) acc1[nt][q] = 0.f;
#pragma unroll
        for (int k0t = 0; k0t < 12; k0t++) {
            int k0 = k0t * 8;
            float a[4];
            a[0] = tnS[m0 * 100 + k0 + qid];
            a[1] = tnS[(m0 + 8) * 100 + k0 + qid];
            a[2] = tnS[m0 * 100 + k0 + qid + 4];
            a[3] = tnS[(m0 + 8) * 100 + k0 + qid + 4];
#pragma unroll
            for (int nt = 0; nt < 12; nt++) {
                int nc = nt * 8 + grp;
                float b0 = wS[(k0 + qid) * 100 + nc];
                float b1 = wS[(k0 + qid + 4) * 100 + nc];
                mma816(acc1[nt], a, b0, b1);
            }
        }
        __syncthreads();

        for (int idx = tid; idx < 2304; idx += 256) {
            int k = idx / 24, ch = idx % 24;
            cp16(smem_u32(wS + k * 100 + ch * 4), g_W2t + (size_t)(c * 96 + k) * 96 + ch * 4, 16);
        }
        CP_COMMIT();
        CP_WAIT0();

#pragma unroll
        for (int nt = 0; nt < 12; nt++)
#pragma unroll
            for (int half = 0; half < 2; half++)
#pragma unroll
                for (int pc = 0; pc < 2; pc++) {
                    int j = nt * 8 + 2 * qid + pc;
                    int row = warp * 16 + grp + 8 * half;
                    float x = acc1[nt][half * 2 + pc] + mb1[c * 96 + j];
                    gS[row * 100 + j] = gelu_ex(x);
                }
        __syncthreads();

#pragma unroll
        for (int k0t = 0; k0t < 12; k0t++) {
            int k0 = k0t * 8;
            float a[4];
            a[0] = gS[m0 * 100 + k0 + qid];
            a[1] = gS[(m0 + 8) * 100 + k0 + qid];
            a[2] = gS[m0 * 100 + k0 + qid + 4];
            a[3] = gS[(m0 + 8) * 100 + k0 + qid + 4];
#pragma unroll
            for (int nt = 0; nt < 12; nt++) {
                int nc = nt * 8 + grp;
                float b0 = wS[(k0 + qid) * 100 + nc];
                float b1 = wS[(k0 + qid + 4) * 100 + nc];
                mma816(acc2[nt], a, b0, b1);
            }
        }
        __syncthreads();
    }

#pragma unroll
    for (int half = 0; half < 2; half++) {
        int row = warp * 16 + grp + 8 * half;
        size_t tok = (size_t)(tokbase + row);
        const float* tsrc = g_tokB + tok * 96;
        float* dst = g_tokA + tok * 96;
#pragma unroll
        for (int nt = 0; nt < 12; nt++)
#pragma unroll
            for (int pc = 0; pc < 2; pc++) {
                int co = nt * 8 + 2 * qid + pc;
                dst[co] = tsrc[co] + acc2[nt][half * 2 + pc] + mb2[co];
            }
    }
}

// ---------------- transpose token-major -> CHW ----------------
__global__ void k_t2() {
    __shared__ float tile[32][33];
    int b = blockIdx.z, c0 = blockIdx.y * 32, p0 = blockIdx.x * 32;
    int tx = threadIdx.x, ty0 = threadIdx.y;
    for (int yy = ty0; yy < 32; yy += 8)
        tile[yy][tx] = g_tokA[(size_t)(b * HWp + p0 + yy) * 96 + c0 + tx];
    __syncthreads();
    for (int yy = ty0; yy < 32; yy += 8)
        g_cross[(size_t)(b * 96 + c0 + yy) * HWp + p0 + tx] = tile[tx][yy];
}

// ---------------- 2D DCT via mma.sync tf32 (proven R15) ----------------
#define DCT_SMEM ((3 * 128 * 132) * 4)    // 202752 B
__global__ void __launch_bounds__(256, 1)
k_dct() {
    extern __shared__ float smf[];
    float* M1 = smf;
    float* Xs = smf + 16896;
    float* Ys = smf + 33792;
    int tid = threadIdx.x;
    int bc = blockIdx.x;
    int lane = tid & 31, warp = tid >> 5;
    int grp = lane >> 2, qid = lane & 3;
    int m0 = warp * 16 + grp;

    const float* Xsrc = g_cross + (size_t)bc * HWp;
    for (int idx = tid; idx < 4096; idx += 256) {
        int r = idx >> 5, ch = idx & 31;
        cp16(smem_u32(M1 + r * 132 + ch * 4), g_Dt + r * 128 + ch * 4, 16);
        cp16(smem_u32(Xs + r * 132 + ch * 4), Xsrc + r * 128 + ch * 4, 16);
    }
    CP_COMMIT();
    CP_WAIT0();
    __syncthreads();

    {
        float acc[16][4];
#pragma unroll
        for (int nt = 0; nt < 16; nt++)
#pragma unroll
            for (int q = 0; q < 4; q++) acc[nt][q] = 0.f;
        for (int k0t = 0; k0t < 16; k0t++) {
            int k0 = k0t * 8;
            float a[4];
            a[0] = M1[m0 * 132 + k0 + qid];
            a[1] = M1[(m0 + 8) * 132 + k0 + qid];
            a[2] = M1[m0 * 132 + k0 + qid + 4];
            a[3] = M1[(m0 + 8) * 132 + k0 + qid + 4];
#pragma unroll
            for (int nt = 0; nt < 16; nt++) {
                int nc = nt * 8 + grp;
                float b0 = Xs[(k0 + qid) * 132 + nc];
                float b1 = Xs[(k0 + qid + 4) * 132 + nc];
                mma816(acc[nt], a, b0, b1);
            }
        }
#pragma unroll
        for (int nt = 0; nt < 16; nt++)
#pragma unroll
            for (int half = 0; half < 2; half++)
#pragma unroll
                for (int pc = 0; pc < 2; pc++)
                    Ys[(m0 + 8 * half) * 132 + nt * 8 + 2 * qid + pc] = acc[nt][half * 2 + pc];
    }
    __syncthreads();

    for (int idx = tid; idx < 4096; idx += 256) {
        int r = idx >> 5, ch = idx & 31;
        cp16(smem_u32(M1 + r * 132 + ch * 4), g_DT + r * 128 + ch * 4, 16);
    }
    CP_COMMIT();
    CP_WAIT0();
    __syncthreads();

    {
        float acc[16][4];
#pragma unroll
        for (int nt = 0; nt < 16; nt++)
#pragma unroll
            for (int q = 0; q < 4; q++) acc[nt][q] = 0.f;
        for (int k0t = 0; k0t < 16; k0t++) {
            int k0 = k0t * 8;
            float a[4];
            a[0] = Ys[m0 * 132 + k0 + qid];
            a[1] = Ys[(m0 + 8) * 132 + k0 + qid];
            a[2] = Ys[m0 * 132 + k0 + qid + 4];
            a[3] = Ys[(m0 + 8) * 132 + k0 + qid + 4];
#pragma unroll
            for (int nt = 0; nt < 16; nt++) {
                int nc = nt * 8 + grp;
                float b0 = M1[(k0 + qid) * 132 + nc];
                float b1 = M1[(k0 + qid + 4) * 132 + nc];
                mma816(acc[nt], a, b0, b1);
            }
        }
        float* dst = g_dct + (size_t)bc * HWp;
#pragma unroll
        for (int nt = 0; nt < 16; nt++)
#pragma unroll
            for (int half = 0; half < 2; half++)
#pragma unroll
                for (int pc = 0; pc < 2; pc++)
                    dst[(m0 + 8 * half) * 128 + nt * 8 + 2 * qid + pc] = acc[nt][half * 2 + pc];
    }
}

// ---------------- channel-mean |dct| ----------------
__global__ void k_energy() {
    int g = blockIdx.x * blockDim.x + threadIdx.x;
    int b = g >> 12, p4 = g & 4095;
    const float4* base = (const float4*)(g_dct + (size_t)b * 96 * HWp) + p4;
    float4 s = make_float4(0.f, 0.f, 0.f, 0.f);
    for (int c = 0; c < 96; c++) {
        float4 v = base[(size_t)c * 4096];
        s.x += fabsf(v.x); s.y += fabsf(v.y); s.z += fabsf(v.z); s.w += fabsf(v.w);
    }
    float inv = 1.f / 96.f;
    s.x *= inv; s.y *= inv; s.z *= inv; s.w *= inv;
    ((float4*)(g_energy + b * HWp))[p4] = s;
}

// ---------------- top-96 via histogram threshold + rank sort ----------------
__global__ void __launch_bounds__(256)
k_topk(const float* __restrict__ fw1, const float* __restrict__ fb1,
       const float* __restrict__ fw2, const float* __restrict__ fb2) {
    extern __shared__ float e[];
    int* hist = (int*)(e + 16384);
    __shared__ int csum[256];
    __shared__ int s_T, s_cnt;
    __shared__ float tk[96];
    __shared__ float hh[24];
    int b = blockIdx.x, tid = threadIdx.x;

    const float4* src = (const float4*)(g_energy + b * HWp);
    float4* e4 = (float4*)e;
    for (int l = tid; l < 4096; l += 256) e4[l] = src[l];
    for (int l = tid; l < 4096; l += 256) hist[l] = 0;
    __syncthreads();
    for (int l = tid; l < 16384; l += 256) {
        int key = (int)(__float_as_uint(e[l]) >> 19);
        atomicAdd(&hist[key], 1);
    }
    __syncthreads();
    {
        int s = 0;
#pragma unroll
        for (int k = 0; k < 16; k++) s += hist[tid * 16 + k];
        csum[tid] = s;
    }
    __syncthreads();
    if (tid == 0) {
        int run = 0, cstar = 0;
        for (int c = 255; c >= 0; c--) {
            if (run + csum[c] >= 96) { cstar = c; break; }
            run += csum[c];
        }
        int T = cstar * 16;
        for (int k = 15; k >= 0; k--) {
            int bin = cstar * 16 + k;
            if (run + hist[bin] >= 96) { T = bin; break; }
            run += hist[bin];
        }
        s_T = T; s_cnt = 0;
    }
    __syncthreads();
    int T = s_T;
    float* cand = (float*)hist;
    __syncthreads();
    for (int l = tid; l < 16384; l += 256) {
        float v = e[l];
        if ((int)(__float_as_uint(v) >> 19) >= T) {
            int pos = atomicAdd(&s_cnt, 1);
            if (pos < 4096) cand[pos] = v;
        }
    }
    __syncthreads();
    int M = s_cnt; if (M > 4096) M = 4096;
    for (int i = tid; i < M; i += 256) {
        float v = cand[i];
        int r = 0;
        for (int j = 0; j < M; j++) {
            float u = cand[j];
            r += (u > v) || (u == v && j < i);
        }
        if (r < 96) tk[r] = v;
    }
    __syncthreads();
    if (tid < 24) {
        float s = fb1[tid];
        for (int k = 0; k < 96; k++) s += tk[k] * fw1[tid * 96 + k];
        hh[tid] = fmaxf(s, 0.f);
    }
    __syncthreads();
    if (tid == 0) {
        float a = fb2[0];
        for (int j = 0; j < 24; j++) a += hh[j] * fw2[j];
        g_scale[b] = 1.f + 1.f / (1.f + expf(-a));
    }
}

// ---------------- epilogue ----------------
__global__ void k_final(const float* __restrict__ x1, const float* __restrict__ x2,
                        float* __restrict__ out) {
    int i = blockIdx.x * blockDim.x + threadIdx.x;
    float s = g_scale[i / (96 * HWp / 4)];
    float4 c = ((const float4*)g_cross)[i];
    float4 a = ((const float4*)x1)[i];
    float4 b = ((const float4*)x2)[i];
    float4 o1, o2;
    o1.x = a.x + s * c.x; o1.y = a.y + s * c.y; o1.z = a.z + s * c.z; o1.w = a.w + s * c.w;
    o2.x = b.x + s * c.x; o2.y = b.y + s * c.y; o2.z = b.z + s * c.z; o2.w = b.w + s * c.w;
    ((float4*)out)[i]            = o1;
    ((float4*)out)[NTOT / 4 + i] = o2;
}

extern "C" void kernel_launch(void* const* d_in, const int* in_sizes, int n_in,
                              void* d_out, int out_size) {
    const float* x1     = (const float*)d_in[0];
    const float* x2     = (const float*)d_in[1];
    const float* w_tx1  = (const float*)d_in[2];
    const float* lm1    = (const float*)d_in[3];
    const float* theta1 = (const float*)d_in[4];
    const float* w_tx2  = (const float*)d_in[5];
    const float* lm2    = (const float*)d_in[6];
    const float* theta2 = (const float*)d_in[7];
    const float* ln1_g  = (const float*)d_in[8];
    const float* ln1_b  = (const float*)d_in[9];
    const float* qkv_w  = (const float*)d_in[10];
    const float* qkv_b  = (const float*)d_in[11];
    const float* proj_w = (const float*)d_in[12];
    const float* proj_b = (const float*)d_in[13];
    const float* ln2_g  = (const float*)d_in[14];
    const float* ln2_b  = (const float*)d_in[15];
    const float* mlp_w1 = (const float*)d_in[16];
    const float* mlp_b1 = (const float*)d_in[17];
    const float* mlp_w2 = (const float*)d_in[18];
    const float* mlp_b2 = (const float*)d_in[19];
    const float* fc_w1  = (const float*)d_in[20];
    const float* fc_b1  = (const float*)d_in[21];
    const float* fc_w2  = (const float*)d_in[22];
    const float* fc_b2  = (const float*)d_in[23];
    float* out = (float*)d_out;

    cudaFuncSetAttribute(k_conv, cudaFuncAttributeMaxDynamicSharedMemorySize, SMEM_CONV);
    cudaFuncSetAttribute(k_attn, cudaFuncAttributeMaxDynamicSharedMemorySize, ATTN_SMEM);
    cudaFuncSetAttribute(k_mlp,  cudaFuncAttributeMaxDynamicSharedMemorySize, MLP_SMEM);
    cudaFuncSetAttribute(k_dct,  cudaFuncAttributeMaxDynamicSharedMemorySize, DCT_SMEM);
    cudaFuncSetAttribute(k_topk, cudaFuncAttributeMaxDynamicSharedMemorySize, 81920);

    // slot 4 (ncu capture) = k_conv
    k_xT<<<dim3(512, 3, 4), dim3(32, 8)>>>(x1, x2);
    k_wprep<<<36, 256>>>(w_tx1, lm1, theta1, w_tx2, lm2, theta2);
    k_prep2<<<241, 256>>>(qkv_w, qkv_b, proj_w, proj_b, mlp_w1, mlp_w2);
    k_conv<<<dim3(128, 4), 256, SMEM_CONV>>>();
    k_attn<<<512, 256, ATTN_SMEM>>>(ln1_g, ln1_b);
    k_mlp<<<512, 256, MLP_SMEM>>>(ln2_g, ln2_b, mlp_b1, mlp_b2);
    k_init_dct<<<64, 256>>>();
    k_t2<<<dim3(512, 3, 4), dim3(32, 8)>>>();
    k_dct<<<384, 256, DCT_SMEM>>>();
    k_energy<<<64, 256>>>();
    k_topk<<<4, 256, 81920>>>(fc_w1, fc_b1, fc_w2, fc_b2);
    k_final<<<NTOT / 4 / 256, 256>>>(x1, x2, out);
}

// round 17
// speedup vs baseline: 3.0497x; 1.0250x over previous
#include <cuda_runtime.h>
#include <math.h>
#include <stdint.h>

#define Bq   4
#define Cc   96
#define HWp  16384
#define NTOT (Bq*Cc*HWp)

typedef unsigned long long ull;

__device__ __forceinline__ float gelu_ex(float x) {
    return 0.5f * x * (1.f + erff(x * 0.70710678118654752f));
}
__device__ __forceinline__ float tf32r(float x) {
    uint32_t r; asm("cvt.rna.tf32.f32 %0,%1;" : "=r"(r) : "f"(x));
    return __uint_as_float(r);
}
__device__ __forceinline__ unsigned smem_u32(const void* p) {
    return (unsigned)__cvta_generic_to_shared(p);
}
__device__ __forceinline__ void cp16(unsigned dst, const void* src, int n) {
    asm volatile("cp.async.cg.shared.global [%0],[%1],16,%2;" :: "r"(dst), "l"(src), "r"(n));
}
#define CP_COMMIT() asm volatile("cp.async.commit_group;")
#define CP_WAIT0()  asm volatile("cp.async.wait_group 0;")
#define CP_WAIT1()  asm volatile("cp.async.wait_group 1;")

// warp-level tf32 MMA, base-ISA
__device__ __forceinline__ void mma816(float* c, const float* a, float b0, float b1) {
    asm volatile("mma.sync.aligned.m16n8k8.row.col.f32.tf32.tf32.f32 "
        "{%0,%1,%2,%3},{%4,%5,%6,%7},{%8,%9},{%0,%1,%2,%3};"
        : "+f"(c[0]), "+f"(c[1]), "+f"(c[2]), "+f"(c[3])
        : "r"(__float_as_uint(a[0])), "r"(__float_as_uint(a[1])),
          "r"(__float_as_uint(a[2])), "r"(__float_as_uint(a[3])),
          "r"(__float_as_uint(b0)), "r"(__float_as_uint(b1)));
}

// ---------------- device scratch ----------------
__device__ float g_xT1[NTOT];       // token-major tf32(x1)
__device__ float g_xT2[NTOT];       // token-major tf32(x2)
__device__ float g_xsum[NTOT];      // token-major 2*(x1+x2), fp32 exact
__device__ float g_wT[2*3*9*3072];  // conv B tiles [img][kblk][tap][ci32][co96], tf32
__device__ float g_Dt[128*128];     // D row-major [freq][pos]
__device__ float g_DT[128*128];     // D^T row-major [pos][freq]
__device__ float g_Wct[96*96];      // attn B tile [k][co], tf32
__device__ float g_bcomb[96];
__device__ float g_W1t[96*384];     // [k][j] tf32
__device__ float g_W2t[384*96];     // [k][co] tf32
__device__ float g_tokA[NTOT];
__device__ float g_cross[NTOT];
__device__ float g_dct[NTOT];
__device__ float g_energy[Bq*HWp];
__device__ float g_scale[Bq];

// ---------------- transpose CHW->token-major + tf32 + residual sum ----------------
__global__ void k_xT(const float* __restrict__ x1, const float* __restrict__ x2) {
    __shared__ float t1[32][33], t2[32][33];
    int b = blockIdx.z, c0 = blockIdx.y * 32, p0 = blockIdx.x * 32;
    int tx = threadIdx.x, ty = threadIdx.y;
    for (int yy = ty; yy < 32; yy += 8) {
        size_t idx = (size_t)(b * 96 + c0 + yy) * HWp + p0 + tx;
        t1[yy][tx] = x1[idx]; t2[yy][tx] = x2[idx];
    }
    __syncthreads();
    for (int yy = ty; yy < 32; yy += 8) {
        size_t o = (size_t)(b * HWp + p0 + yy) * 96 + c0 + tx;
        float a = t1[tx][yy], bb = t2[tx][yy];
        g_xT1[o] = tf32r(a);
        g_xT2[o] = tf32r(bb);
        g_xsum[o] = 2.f * (a + bb);
    }
}

// ---------------- LDC effective weights -> conv B tiles, tf32 ----------------
__global__ void k_wprep(const float* __restrict__ w1, const float* __restrict__ lm1,
                        const float* __restrict__ th1,
                        const float* __restrict__ w2, const float* __restrict__ lm2,
                        const float* __restrict__ th2) {
    int t = blockIdx.x * 256 + threadIdx.x;
    if (t >= 96 * 96) return;
    int co = t / 96, ci = t % 96;
#pragma unroll
    for (int img = 0; img < 2; img++) {
        const float* ws = (img ? w2 : w1) + t * 9;
        const float* lm = img ? lm2 : lm1;
        float theta = img ? th2[0] : th1[0];
        float s = 0.f;
#pragma unroll
        for (int k = 0; k < 9; k++) s += ws[k];
        float sc = 1.f - theta * lm[t] * s;
#pragma unroll
        for (int tap = 0; tap < 9; tap++) {
            float v = ws[tap];
            if (tap == 4) v *= sc;
            g_wT[(size_t)((img * 3 + (ci >> 5)) * 9 + tap) * 3072 + (ci & 31) * 96 + co] = tf32r(v);
        }
    }
}

// ---------------- init: DCT-II matrices ----------------
__global__ void k_init_dct() {
    int t = blockIdx.x * blockDim.x + threadIdx.x;
    int k = t >> 7, i = t & 127;
    float arg = (float)((2 * i + 1) * k) * (1.0f / 256.0f);
    float v = cospif(arg) * 0.125f;
    if (k == 0) v *= 0.70710678118654752440f;
    g_Dt[k * 128 + i] = v;
    g_DT[i * 128 + k] = v;
}

// ---------------- prep: Wcomb tf32, bcomb, MLP tf32 transposes ----------------
__global__ void k_prep2(const float* __restrict__ qkv_w, const float* __restrict__ qkv_b,
                        const float* __restrict__ proj_w, const float* __restrict__ proj_b,
                        const float* __restrict__ w1, const float* __restrict__ w2) {
    int blk = blockIdx.x, tid = threadIdx.x;
    if (blk < 96) {
        if (tid < 96) {
            float s = 0.f;
            for (int m = 0; m < 96; m++)
                s += proj_w[blk * 96 + m] * qkv_w[(192 + m) * 96 + tid];
            g_Wct[tid * 96 + blk] = tf32r(s);
        }
    } else if (blk == 96) {
        if (tid < 96) {
            float s = proj_b[tid];
            for (int m = 0; m < 96; m++)
                s += proj_w[tid * 96 + m] * qkv_b[192 + m];
            g_bcomb[tid] = s;
        }
    } else {
        int t = (blk - 97) * 256 + tid;
        if (t < 96 * 384) {
            { int k = t / 384, j = t % 384; g_W1t[t] = tf32r(w1[j * 96 + k]); }
            { int k = t / 96,  i = t % 96;  g_W2t[t] = tf32r(w2[i * 384 + k]); }
        }
    }
}

// ---------------- tensor-core conv, double-buffered per-tap B ----------------
#define A_PLANE (130*36)
#define SM_A_FLOATS (3*A_PLANE)                         // 14040
#define SMEM_CONV ((SM_A_FLOATS + 2*3200) * 4)          // 81760
__global__ void __launch_bounds__(256, 2)
k_conv() {
    extern __shared__ float smf[];
    float* As = smf;
    float* Bs = smf + SM_A_FLOATS;                      // [2][32][100]
    int tid = threadIdx.x;
    int y = blockIdx.x, b = blockIdx.y;
    int lane = tid & 31, wid = tid >> 5;
    int grp = lane >> 2, qid = lane & 3;
    int m_base = (wid >> 1) * 32;
    int n_base = (wid & 1) * 48;

    float acc[2][6][4];
#pragma unroll
    for (int mt = 0; mt < 2; mt++)
#pragma unroll
        for (int nt = 0; nt < 6; nt++)
#pragma unroll
            for (int q = 0; q < 4; q++) acc[mt][nt][q] = 0.f;

    auto issueA = [&](int s) {
        int img = s / 3, kblk = s % 3;
        const float* base = (img ? g_xT2 : g_xT1) + (size_t)b * HWp * 96 + kblk * 32;
        for (int idx = tid; idx < 3120; idx += 256) {
            int r = idx >> 3, c4 = idx & 7;
            int dy = r / 130, pxi = r % 130;
            int x = pxi - 1;
            int yy = y + dy - 1;
            bool ok = (x >= 0) && (x < 128) && (yy >= 0) && (yy < 128);
            const float* src = base + (size_t)((ok ? yy : 0) * 128 + (ok ? x : 0)) * 96 + c4 * 4;
            cp16(smem_u32(As + dy * A_PLANE + pxi * 36 + c4 * 4), src, ok ? 16 : 0);
        }
    };
    auto issueB = [&](int t, int buf) {
        int s = t / 9, tap = t % 9;
        int img = s / 3, kblk = s % 3;
        const float* wsrc = g_wT + (size_t)((img * 3 + kblk) * 9 + tap) * 3072;
        for (int idx = tid; idx < 768; idx += 256) {
            int k = idx / 24, ch = idx % 24;
            cp16(smem_u32(Bs + buf * 3200 + k * 100 + ch * 4), wsrc + k * 96 + ch * 4, 16);
        }
    };

    issueA(0);
    issueB(0, 0);
    CP_COMMIT();
    int buf = 0;

    for (int t = 0; t < 54; t++) {
        int s = t / 9, tap = t % 9;
        bool lastInS = (tap == 8);
        bool pre = (t + 1 < 54) && !lastInS;
        if (pre) { issueB(t + 1, buf ^ 1); CP_COMMIT(); }
        if (pre) CP_WAIT1(); else CP_WAIT0();
        __syncthreads();

        int dy = tap / 3, dx = tap % 3 - 1;
        const float* Ap = As + dy * A_PLANE;
        const float* Bp = Bs + buf * 3200;
#pragma unroll
        for (int kk = 0; kk < 4; kk++) {
            int k0 = kk * 8;
            float a[2][4];
#pragma unroll
            for (int mt = 0; mt < 2; mt++) {
                int m0 = m_base + mt * 16 + grp + dx + 1;
                a[mt][0] = Ap[m0 * 36 + k0 + qid];
                a[mt][1] = Ap[(m0 + 8) * 36 + k0 + qid];
                a[mt][2] = Ap[m0 * 36 + k0 + qid + 4];
                a[mt][3] = Ap[(m0 + 8) * 36 + k0 + qid + 4];
            }
#pragma unroll
            for (int nt = 0; nt < 6; nt++) {
                int nc = n_base + nt * 8 + grp;
                float b0 = Bp[(k0 + qid) * 100 + nc];
                float b1 = Bp[(k0 + qid + 4) * 100 + nc];
                mma816(acc[0][nt], a[0], b0, b1);
                mma816(acc[1][nt], a[1], b0, b1);
            }
        }
        __syncthreads();

        if (pre) buf ^= 1;
        if (lastInS && t + 1 < 54) {
            issueA(s + 1);
            issueB(t + 1, buf);   // reuse just-consumed buffer
            CP_COMMIT();
        }
    }

    size_t tokbase = (size_t)b * HWp + (size_t)y * 128;
#pragma unroll
    for (int mt = 0; mt < 2; mt++) {
#pragma unroll
        for (int half = 0; half < 2; half++) {
            int m = m_base + mt * 16 + grp + half * 8;
            float* dst = g_tokA + (tokbase + m) * 96;
            const float* xs = g_xsum + (tokbase + m) * 96;
#pragma unroll
            for (int nt = 0; nt < 6; nt++) {
                int co = n_base + nt * 8 + 2 * qid;
                float2 sv = *(const float2*)(xs + co);
                float2 o;
                o.x = acc[mt][nt][half * 2 + 0] + sv.x;
                o.y = acc[mt][nt][half * 2 + 1] + sv.y;
                *(float2*)(dst + co) = o;
            }
        }
    }
}

// ---------------- fused swin block (attn + MLP) via mma.sync tf32 ----------------
// tnS: LN output; wS: shared weight tile; gS: t2 (attn out); hS: gelu
#define BLK_SMEM (48000 * 4)    // 192000 B
__global__ void __launch_bounds__(256, 1)
k_block(const float* __restrict__ g1, const float* __restrict__ b1,
        const float* __restrict__ g2, const float* __restrict__ b2,
        const float* __restrict__ mb1, const float* __restrict__ mb2) {
    extern __shared__ float smf[];
    float* tnS = smf;            // [128][100]
    float* wS  = smf + 12800;    // [96][100]
    float* gS  = smf + 22400;    // [128][100]  t2
    float* hS  = smf + 35200;    // [128][100]  gelu
    int tid = threadIdx.x;
    int warp = tid >> 5, lane = tid & 31;
    int grp = lane >> 2, qid = lane & 3;
    int tokbase = blockIdx.x * 128;
    int m0 = warp * 16 + grp;

    // stage Wcomb (overlaps LN1)
    for (int idx = tid; idx < 2304; idx += 256) {
        int k = idx / 24, ch = idx % 24;
        cp16(smem_u32(wS + k * 100 + ch * 4), g_Wct + k * 96 + ch * 4, 16);
    }
    CP_COMMIT();

    // LN1 from g_tokA -> tnS
    for (int t = 0; t < 16; t++) {
        int tok = warp * 16 + t;
        const float* tp = g_tokA + (size_t)(tokbase + tok) * 96;
        float a = tp[lane], bb = tp[lane + 32], cc = tp[lane + 64];
        float s = a + bb + cc;
#pragma unroll
        for (int o = 16; o; o >>= 1) s += __shfl_xor_sync(0xffffffff, s, o);
        float m = s * (1.f / 96.f);
        float d0 = a - m, d1 = bb - m, d2 = cc - m;
        float q = d0 * d0 + d1 * d1 + d2 * d2;
#pragma unroll
        for (int o = 16; o; o >>= 1) q += __shfl_xor_sync(0xffffffff, q, o);
        float rstd = rsqrtf(q * (1.f / 96.f) + 1e-5f);
        tnS[tok * 100 + lane]      = d0 * rstd * g1[lane]      + b1[lane];
        tnS[tok * 100 + lane + 32] = d1 * rstd * g1[lane + 32] + b1[lane + 32];
        tnS[tok * 100 + lane + 64] = d2 * rstd * g1[lane + 64] + b1[lane + 64];
    }
    CP_WAIT0();
    __syncthreads();

    // attn GEMM
    float acc[12][4];
#pragma unroll
    for (int nt = 0; nt < 12; nt++)
#pragma unroll
        for (int q = 0; q < 4; q++) acc[nt][q] = 0.f;
#pragma unroll
    for (int k0t = 0; k0t < 12; k0t++) {
        int k0 = k0t * 8;
        float a[4];
        a[0] = tnS[m0 * 100 + k0 + qid];
        a[1] = tnS[(m0 + 8) * 100 + k0 + qid];
        a[2] = tnS[m0 * 100 + k0 + qid + 4];
        a[3] = tnS[(m0 + 8) * 100 + k0 + qid + 4];
#pragma unroll
        for (int nt = 0; nt < 12; nt++) {
            int nc = nt * 8 + grp;
            float b0 = wS[(k0 + qid) * 100 + nc];
            float b1 = wS[(k0 + qid + 4) * 100 + nc];
            mma816(acc[nt], a, b0, b1);
        }
    }
    __syncthreads();   // wS reads done (safe to re-stage later)

    // t2 = tokA + attn + bcomb -> gS (warp-local rows)
#pragma unroll
    for (int half = 0; half < 2; half++) {
        int row = warp * 16 + grp + 8 * half;
        const float* tsrc = g_tokA + (size_t)(tokbase + row) * 96;
#pragma unroll
        for (int nt = 0; nt < 12; nt++)
#pragma unroll
            for (int pc = 0; pc < 2; pc++) {
                int co = nt * 8 + 2 * qid + pc;
                gS[row * 100 + co] = tsrc[co] + acc[nt][half * 2 + pc] + g_bcomb[co];
            }
    }
    __syncwarp();

    // LN2 from gS -> tnS (warp-local rows; tnS attn reads were own-warp too)
    for (int t = 0; t < 16; t++) {
        int tok = warp * 16 + t;
        float a = gS[tok * 100 + lane], bb = gS[tok * 100 + lane + 32], cc = gS[tok * 100 + lane + 64];
        float s = a + bb + cc;
#pragma unroll
        for (int o = 16; o; o >>= 1) s += __shfl_xor_sync(0xffffffff, s, o);
        float m = s * (1.f / 96.f);
        float d0 = a - m, d1 = bb - m, d2 = cc - m;
        float q = d0 * d0 + d1 * d1 + d2 * d2;
#pragma unroll
        for (int o = 16; o; o >>= 1) q += __shfl_xor_sync(0xffffffff, q, o);
        float rstd = rsqrtf(q * (1.f / 96.f) + 1e-5f);
        tnS[tok * 100 + lane]      = d0 * rstd * g2[lane]      + b2[lane];
        tnS[tok * 100 + lane + 32] = d1 * rstd * g2[lane + 32] + b2[lane + 32];
        tnS[tok * 100 + lane + 64] = d2 * rstd * g2[lane + 64] + b2[lane + 64];
    }

    // MLP chunks
    float acc2[12][4];
#pragma unroll
    for (int nt = 0; nt < 12; nt++)
#pragma unroll
        for (int q = 0; q < 4; q++) acc2[nt][q] = 0.f;

    for (int c = 0; c < 4; c++) {
        for (int idx = tid; idx < 2304; idx += 256) {
            int k = idx / 24, ch = idx % 24;
            cp16(smem_u32(wS + k * 100 + ch * 4), g_W1t + k * 384 + c * 96 + ch * 4, 16);
        }
        CP_COMMIT();
        CP_WAIT0();
        __syncthreads();

        float acc1[12][4];
#pragma unroll
        for (int nt = 0; nt < 12; nt++)
#pragma unroll
            for (int q = 0; q < 4; q++) acc1[nt][q] = 0.f;
#pragma unroll
        for (int k0t = 0; k0t < 12; k0t++) {
            int k0 = k0t * 8;
            float a[4];
            a[0] = tnS[m0 * 100 + k0 + qid];
            a[1] = tnS[(m0 + 8) * 100 + k0 + qid];
            a[2] = tnS[m0 * 100 + k0 + qid + 4];
            a[3] = tnS[(m0 + 8) * 100 + k0 + qid + 4];
#pragma unroll
            for (int nt = 0; nt < 12; nt++) {
                int nc = nt * 8 + grp;
                float b0 = wS[(k0 + qid) * 100 + nc];
                float b1 = wS[(k0 + qid + 4) * 100 + nc];
                mma816(acc1[nt], a, b0, b1);
            }
        }
        __syncthreads();

        for (int idx = tid; idx < 2304; idx += 256) {
            int k = idx / 24, ch = idx % 24;
            cp16(smem_u32(wS + k * 100 + ch * 4), g_W2t + (size_t)(c * 96 + k) * 96 + ch * 4, 16);
        }
        CP_COMMIT();
        CP_WAIT0();

#pragma unroll
        for (int nt = 0; nt < 12; nt++)
#pragma unroll
            for (int half = 0; half < 2; half++)
#pragma unroll
                for (int pc = 0; pc < 2; pc++) {
                    int j = nt * 8 + 2 * qid + pc;
                    int row = warp * 16 + grp + 8 * half;
                    float x = acc1[nt][half * 2 + pc] + mb1[c * 96 + j];
                    hS[row * 100 + j] = gelu_ex(x);
                }
        __syncthreads();

#pragma unroll
        for (int k0t = 0; k0t < 12; k0t++) {
            int k0 = k0t * 8;
            float a[4];
            a[0] = hS[m0 * 100 + k0 + qid];
            a[1] = hS[(m0 + 8) * 100 + k0 + qid];
            a[2] = hS[m0 * 100 + k0 + qid + 4];
            a[3] = hS[(m0 + 8) * 100 + k0 + qid + 4];
#pragma unroll
            for (int nt = 0; nt < 12; nt++) {
                int nc = nt * 8 + grp;
                float b0 = wS[(k0 + qid) * 100 + nc];
                float b1 = wS[(k0 + qid + 4) * 100 + nc];
                mma816(acc2[nt], a, b0, b1);
            }
        }
        __syncthreads();
    }

    // epilogue: out = t2 + O + mb2 -> g_tokA
#pragma unroll
    for (int half = 0; half < 2; half++) {
        int row = warp * 16 + grp + 8 * half;
        size_t tok = (size_t)(tokbase + row);
        float* dst = g_tokA + tok * 96;
#pragma unroll
        for (int nt = 0; nt < 12; nt++)
#pragma unroll
            for (int pc = 0; pc < 2; pc++) {
                int co = nt * 8 + 2 * qid + pc;
                dst[co] = gS[row * 100 + co] + acc2[nt][half * 2 + pc] + mb2[co];
            }
    }
}

// ---------------- transpose token-major -> CHW ----------------
__global__ void k_t2() {
    __shared__ float tile[32][33];
    int b = blockIdx.z, c0 = blockIdx.y * 32, p0 = blockIdx.x * 32;
    int tx = threadIdx.x, ty0 = threadIdx.y;
    for (int yy = ty0; yy < 32; yy += 8)
        tile[yy][tx] = g_tokA[(size_t)(b * HWp + p0 + yy) * 96 + c0 + tx];
    __syncthreads();
    for (int yy = ty0; yy < 32; yy += 8)
        g_cross[(size_t)(b * 96 + c0 + yy) * HWp + p0 + tx] = tile[tx][yy];
}

// ---------------- 2D DCT via mma.sync tf32 ----------------
#define DCT_SMEM ((3 * 128 * 132) * 4)    // 202752 B
__global__ void __launch_bounds__(256, 1)
k_dct() {
    extern __shared__ float smf[];
    float* M1 = smf;
    float* Xs = smf + 16896;
    float* Ys = smf + 33792;
    int tid = threadIdx.x;
    int bc = blockIdx.x;
    int lane = tid & 31, warp = tid >> 5;
    int grp = lane >> 2, qid = lane & 3;
    int m0 = warp * 16 + grp;

    const float* Xsrc = g_cross + (size_t)bc * HWp;
    for (int idx = tid; idx < 4096; idx += 256) {
        int r = idx >> 5, ch = idx & 31;
        cp16(smem_u32(M1 + r * 132 + ch * 4), g_Dt + r * 128 + ch * 4, 16);
        cp16(smem_u32(Xs + r * 132 + ch * 4), Xsrc + r * 128 + ch * 4, 16);
    }
    CP_COMMIT();
    CP_WAIT0();
    __syncthreads();

    {
        float acc[16][4];
#pragma unroll
        for (int nt = 0; nt < 16; nt++)
#pragma unroll
            for (int q = 0; q < 4; q++) acc[nt][q] = 0.f;
        for (int k0t = 0; k0t < 16; k0t++) {
            int k0 = k0t * 8;
            float a[4];
            a[0] = M1[m0 * 132 + k0 + qid];
            a[1] = M1[(m0 + 8) * 132 + k0 + qid];
            a[2] = M1[m0 * 132 + k0 + qid + 4];
            a[3] = M1[(m0 + 8) * 132 + k0 + qid + 4];
#pragma unroll
            for (int nt = 0; nt < 16; nt++) {
                int nc = nt * 8 + grp;
                float b0 = Xs[(k0 + qid) * 132 + nc];
                float b1 = Xs[(k0 + qid + 4) * 132 + nc];
                mma816(acc[nt], a, b0, b1);
            }
        }
#pragma unroll
        for (int nt = 0; nt < 16; nt++)
#pragma unroll
            for (int half = 0; half < 2; half++)
#pragma unroll
                for (int pc = 0; pc < 2; pc++)
                    Ys[(m0 + 8 * half) * 132 + nt * 8 + 2 * qid + pc] = acc[nt][half * 2 + pc];
    }
    __syncthreads();

    for (int idx = tid; idx < 4096; idx += 256) {
        int r = idx >> 5, ch = idx & 31;
        cp16(smem_u32(M1 + r * 132 + ch * 4), g_DT + r * 128 + ch * 4, 16);
    }
    CP_COMMIT();
    CP_WAIT0();
    __syncthreads();

    {
        float acc[16][4];
#pragma unroll
        for (int nt = 0; nt < 16; nt++)
#pragma unroll
            for (int q = 0; q < 4; q++) acc[nt][q] = 0.f;
        for (int k0t = 0; k0t < 16; k0t++) {
            int k0 = k0t * 8;
            float a[4];
            a[0] = Ys[m0 * 132 + k0 + qid];
            a[1] = Ys[(m0 + 8) * 132 + k0 + qid];
            a[2] = Ys[m0 * 132 + k0 + qid + 4];
            a[3] = Ys[(m0 + 8) * 132 + k0 + qid + 4];
#pragma unroll
            for (int nt = 0; nt < 16; nt++) {
                int nc = nt * 8 + grp;
                float b0 = M1[(k0 + qid) * 132 + nc];
                float b1 = M1[(k0 + qid + 4) * 132 + nc];
                mma816(acc[nt], a, b0, b1);
            }
        }
        float* dst = g_dct + (size_t)bc * HWp;
#pragma unroll
        for (int nt = 0; nt < 16; nt++)
#pragma unroll
            for (int half = 0; half < 2; half++)
#pragma unroll
                for (int pc = 0; pc < 2; pc++)
                    dst[(m0 + 8 * half) * 128 + nt * 8 + 2 * qid + pc] = acc[nt][half * 2 + pc];
    }
}

// ---------------- channel-mean |dct| ----------------
__global__ void k_energy() {
    int g = blockIdx.x * blockDim.x + threadIdx.x;
    int b = g >> 12, p4 = g & 4095;
    const float4* base = (const float4*)(g_dct + (size_t)b * 96 * HWp) + p4;
    float4 s = make_float4(0.f, 0.f, 0.f, 0.f);
    for (int c = 0; c < 96; c++) {
        float4 v = base[(size_t)c * 4096];
        s.x += fabsf(v.x); s.y += fabsf(v.y); s.z += fabsf(v.z); s.w += fabsf(v.w);
    }
    float inv = 1.f / 96.f;
    s.x *= inv; s.y *= inv; s.z *= inv; s.w *= inv;
    ((float4*)(g_energy + b * HWp))[p4] = s;
}

// ---------------- top-96 via histogram threshold + rank sort ----------------
__global__ void __launch_bounds__(256)
k_topk(const float* __restrict__ fw1, const float* __restrict__ fb1,
       const float* __restrict__ fw2, const float* __restrict__ fb2) {
    extern __shared__ float e[];
    int* hist = (int*)(e + 16384);
    __shared__ int csum[256];
    __shared__ int s_T, s_cnt;
    __shared__ float tk[96];
    __shared__ float hh[24];
    int b = blockIdx.x, tid = threadIdx.x;

    const float4* src = (const float4*)(g_energy + b * HWp);
    float4* e4 = (float4*)e;
    for (int l = tid; l < 4096; l += 256) e4[l] = src[l];
    for (int l = tid; l < 4096; l += 256) hist[l] = 0;
    __syncthreads();
    for (int l = tid; l < 16384; l += 256) {
        int key = (int)(__float_as_uint(e[l]) >> 19);
        atomicAdd(&hist[key], 1);
    }
    __syncthreads();
    {
        int s = 0;
#pragma unroll
        for (int k = 0; k < 16; k++) s += hist[tid * 16 + k];
        csum[tid] = s;
    }
    __syncthreads();
    if (tid == 0) {
        int run = 0, cstar = 0;
        for (int c = 255; c >= 0; c--) {
            if (run + csum[c] >= 96) { cstar = c; break; }
            run += csum[c];
        }
        int T = cstar * 16;
        for (int k = 15; k >= 0; k--) {
            int bin = cstar * 16 + k;
            if (run + hist[bin] >= 96) { T = bin; break; }
            run += hist[bin];
        }
        s_T = T; s_cnt = 0;
    }
    __syncthreads();
    int T = s_T;
    float* cand = (float*)hist;
    __syncthreads();
    for (int l = tid; l < 16384; l += 256) {
        float v = e[l];
        if ((int)(__float_as_uint(v) >> 19) >= T) {
            int pos = atomicAdd(&s_cnt, 1);
            if (pos < 4096) cand[pos] = v;
        }
    }
    __syncthreads();
    int M = s_cnt; if (M > 4096) M = 4096;
    for (int i = tid; i < M; i += 256) {
        float v = cand[i];
        int r = 0;
        for (int j = 0; j < M; j++) {
            float u = cand[j];
            r += (u > v) || (u == v && j < i);
        }
        if (r < 96) tk[r] = v;
    }
    __syncthreads();
    if (tid < 24) {
        float s = fb1[tid];
        for (int k = 0; k < 96; k++) s += tk[k] * fw1[tid * 96 + k];
        hh[tid] = fmaxf(s, 0.f);
    }
    __syncthreads();
    if (tid == 0) {
        float a = fb2[0];
        for (int j = 0; j < 24; j++) a += hh[j] * fw2[j];
        g_scale[b] = 1.f + 1.f / (1.f + expf(-a));
    }
}

// ---------------- epilogue ----------------
__global__ void k_final(const float* __restrict__ x1, const float* __restrict__ x2,
                        float* __restrict__ out) {
    int i = blockIdx.x * blockDim.x + threadIdx.x;
    float s = g_scale[i / (96 * HWp / 4)];
    float4 c = ((const float4*)g_cross)[i];
    float4 a = ((const float4*)x1)[i];
    float4 b = ((const float4*)x2)[i];
    float4 o1, o2;
    o1.x = a.x + s * c.x; o1.y = a.y + s * c.y; o1.z = a.z + s * c.z; o1.w = a.w + s * c.w;
    o2.x = b.x + s * c.x; o2.y = b.y + s * c.y; o2.z = b.z + s * c.z; o2.w = b.w + s * c.w;
    ((float4*)out)[i]            = o1;
    ((float4*)out)[NTOT / 4 + i] = o2;
}

extern "C" void kernel_launch(void* const* d_in, const int* in_sizes, int n_in,
                              void* d_out, int out_size) {
    const float* x1     = (const float*)d_in[0];
    const float* x2     = (const float*)d_in[1];
    const float* w_tx1  = (const float*)d_in[2];
    const float* lm1    = (const float*)d_in[3];
    const float* theta1 = (const float*)d_in[4];
    const float* w_tx2  = (const float*)d_in[5];
    const float* lm2    = (const float*)d_in[6];
    const float* theta2 = (const float*)d_in[7];
    const float* ln1_g  = (const float*)d_in[8];
    const float* ln1_b  = (const float*)d_in[9];
    const float* qkv_w  = (const float*)d_in[10];
    const float* qkv_b  = (const float*)d_in[11];
    const float* proj_w = (const float*)d_in[12];
    const float* proj_b = (const float*)d_in[13];
    const float* ln2_g  = (const float*)d_in[14];
    const float* ln2_b  = (const float*)d_in[15];
    const float* mlp_w1 = (const float*)d_in[16];
    const float* mlp_b1 = (const float*)d_in[17];
    const float* mlp_w2 = (const float*)d_in[18];
    const float* mlp_b2 = (const float*)d_in[19];
    const float* fc_w1  = (const float*)d_in[20];
    const float* fc_b1  = (const float*)d_in[21];
    const float* fc_w2  = (const float*)d_in[22];
    const float* fc_b2  = (const float*)d_in[23];
    float* out = (float*)d_out;

    cudaFuncSetAttribute(k_conv,  cudaFuncAttributeMaxDynamicSharedMemorySize, SMEM_CONV);
    cudaFuncSetAttribute(k_block, cudaFuncAttributeMaxDynamicSharedMemorySize, BLK_SMEM);
    cudaFuncSetAttribute(k_dct,   cudaFuncAttributeMaxDynamicSharedMemorySize, DCT_SMEM);
    cudaFuncSetAttribute(k_topk,  cudaFuncAttributeMaxDynamicSharedMemorySize, 81920);

    // slot 4 (ncu capture) = k_conv
    k_xT<<<dim3(512, 3, 4), dim3(32, 8)>>>(x1, x2);
    k_wprep<<<36, 256>>>(w_tx1, lm1, theta1, w_tx2, lm2, theta2);
    k_prep2<<<241, 256>>>(qkv_w, qkv_b, proj_w, proj_b, mlp_w1, mlp_w2);
    k_conv<<<dim3(128, 4), 256, SMEM_CONV>>>();
    k_block<<<512, 256, BLK_SMEM>>>(ln1_g, ln1_b, ln2_g, ln2_b, mlp_b1, mlp_b2);
    k_init_dct<<<64, 256>>>();
    k_t2<<<dim3(512, 3, 4), dim3(32, 8)>>>();
    k_dct<<<384, 256, DCT_SMEM>>>();
    k_energy<<<64, 256>>>();
    k_topk<<<4, 256, 81920>>>(fc_w1, fc_b1, fc_w2, fc_b2);
    k_final<<<NTOT / 4 / 256, 256>>>(x1, x2, out);
}